// round 14
// baseline (speedup 1.0000x reference)
#include <cuda_runtime.h>
#include <cuda_fp16.h>
#include <math.h>
#include <stdint.h>

#define B_  2
#define S_  2048
#define E_  2048
#define H_  16
#define G_  4
#define HD_ 128
#define GD_ 512
#define MTOT (B_*S_)

// ---------------- device scratch (allocation-free rule) ----------------
__device__ __half g_Q [(size_t)B_*H_*S_*HD_];
__device__ __half g_K [(size_t)B_*G_*S_*HD_];
__device__ __half g_Vt[(size_t)B_*G_*HD_*S_];
__device__ __half g_O [(size_t)B_*S_*E_];
__device__ __half g_Xr[(size_t)B_*S_*E_];
__device__ __half g_WqT[(size_t)E_*E_];
__device__ __half g_WkT[(size_t)GD_*E_];
__device__ __half g_WvT[(size_t)GD_*E_];
__device__ __half g_WoT[(size_t)E_*E_];
__device__ unsigned long long g_MB[(size_t)B_*S_*32];

// ---------------- helpers ----------------
__device__ __forceinline__ uint32_t smem_u32(const void* p) {
    uint32_t a;
    asm("{ .reg .u64 t; cvta.to.shared.u64 t, %1; cvt.u32.u64 %0, t; }" : "=r"(a) : "l"(p));
    return a;
}
__device__ __forceinline__ uint32_t pack_h2(float lo, float hi) {
    __half2 v = __floats2half2_rn(lo, hi);
    return *reinterpret_cast<uint32_t*>(&v);
}
__device__ __forceinline__ uint32_t ex2_h2(uint32_t in) {
    uint32_t r;
    asm("ex2.approx.f16x2 %0, %1;" : "=r"(r) : "r"(in));
    return r;
}

#define CP_ASYNC16(dst, src) \
    asm volatile("cp.async.cg.shared.global [%0], [%1], 16;" :: "r"(dst), "l"(src) : "memory")
#define CP_COMMIT() asm volatile("cp.async.commit_group;" ::: "memory")
#define CP_WAIT1()  asm volatile("cp.async.wait_group 1;"  ::: "memory")

__device__ __forceinline__ void mma_f16(float& d0, float& d1, float& d2, float& d3,
                                        uint32_t a0, uint32_t a1, uint32_t a2, uint32_t a3,
                                        uint32_t b0, uint32_t b1) {
    asm volatile("mma.sync.aligned.m16n8k16.row.col.f32.f16.f16.f32 "
                 "{%0,%1,%2,%3},{%4,%5,%6,%7},{%8,%9},{%0,%1,%2,%3};"
                 : "+f"(d0), "+f"(d1), "+f"(d2), "+f"(d3)
                 : "r"(a0), "r"(a1), "r"(a2), "r"(a3), "r"(b0), "r"(b1));
}
__device__ __forceinline__ void ldsm_x4(uint32_t& r0, uint32_t& r1, uint32_t& r2, uint32_t& r3,
                                        uint32_t addr) {
    asm volatile("ldmatrix.sync.aligned.m8n8.x4.shared.b16 {%0,%1,%2,%3}, [%4];"
                 : "=r"(r0), "=r"(r1), "=r"(r2), "=r"(r3) : "r"(addr));
}

// ---------------------------------------------------------------------------
// Prep kernels
// ---------------------------------------------------------------------------
__global__ void prep_w(const float* __restrict__ Wq, const float* __restrict__ Wk,
                       const float* __restrict__ Wv, const float* __restrict__ Wo) {
    __shared__ float tt[32][33];
    const int z = blockIdx.z;
    const int tx = threadIdx.x, ty = threadIdx.y;
    const float* in; __half* out; int Cc;
    if      (z == 0) { in = Wq; out = g_WqT; Cc = E_;  }
    else if (z == 1) { in = Wk; out = g_WkT; Cc = GD_; }
    else if (z == 2) { in = Wv; out = g_WvT; Cc = GD_; }
    else             { in = Wo; out = g_WoT; Cc = E_;  }
    const int c0 = blockIdx.x * 32, r0 = blockIdx.y * 32;
    if (c0 >= Cc) return;
    #pragma unroll
    for (int i = ty; i < 32; i += 8)
        tt[i][tx] = in[(size_t)(r0 + i) * Cc + c0 + tx];
    __syncthreads();
    #pragma unroll
    for (int i = ty; i < 32; i += 8)
        out[(size_t)(c0 + i) * E_ + r0 + tx] = __float2half_rn(tt[tx][i]);
}

__global__ void f2h_copy(const float* __restrict__ in, __half* __restrict__ out) {
    const size_t i = (size_t)blockIdx.x * 256 + threadIdx.x;
    float2 v = *(const float2*)(in + 2*i);
    *(uint32_t*)(out + 2*i) = pack_h2(v.x, v.y);
}

__global__ void mask_pack(const int* __restrict__ mask) {
    const size_t i = (size_t)blockIdx.x * 256 + threadIdx.x;
    const unsigned v = (mask[i] != 0) ? 1u : 0u;
    const unsigned bal = __ballot_sync(0xffffffffu, v);
    if ((threadIdx.x & 31) == 0)
        ((uint32_t*)g_MB)[i >> 5] = bal;
}

// ---------------------------------------------------------------------------
// Fused QKV GEMM (best config, unchanged)
// ---------------------------------------------------------------------------
#define GROW_H 72
#define GROWB  144
#define GSTG_B (128*GROW_H*2)
#define GSTG_PAIR (2*GSTG_B)
#define GEMM_SMEM (3*GSTG_PAIR)      // 110592

__global__ __launch_bounds__(256, 2)
void qkv_gemm(const float* __restrict__ bq, const float* __restrict__ bk,
              const float* __restrict__ bv) {
    extern __shared__ __align__(16) unsigned char gsm[];
    const uint32_t smb = smem_u32(gsm);

    const int t    = threadIdx.x;
    const int lane = t & 31;
    const int wid  = t >> 5;
    const int wm   = wid & 3;
    const int wn   = wid >> 2;
    const int gq   = lane >> 2;
    const int tr   = lane & 3;
    const int lrow = lane & 7, lmat = lane >> 3;
    const int bx = blockIdx.x;
    const int m0 = blockIdx.y * 128;

    const __half* Bw; const float* bias; int nt, heads, vmode;
    if (bx < 16)      { Bw = g_WqT; bias = bq; nt = bx;      heads = 16; vmode = 0; }
    else if (bx < 20) { Bw = g_WkT; bias = bk; nt = bx - 16; heads = 4;  vmode = 0; }
    else              { Bw = g_WvT; bias = bv; nt = bx - 20; heads = 4;  vmode = 1; }
    const int n0 = nt * 128;
    const int K = E_;

    const int row8 = t >> 3, chk = t & 7;
    const __half* Agr = g_Xr + (size_t)(m0 + row8) * K + chk*8;
    const __half* Bgr = Bw   + (size_t)(n0 + row8) * K + chk*8;
    const uint32_t dA = smb + (uint32_t)(row8*GROWB + chk*16);
    const uint32_t dB = dA + GSTG_B;

    const uint32_t aoff = (uint32_t)(((wm*32 + (lmat&1)*8 + lrow)*GROW_H + (lmat>>1)*8) * 2);
    const uint32_t boff = (uint32_t)(((wn*64 + (lmat>>1)*8 + lrow)*GROW_H + (lmat&1)*8) * 2) + GSTG_B;

    float acc[2][8][4];
    #pragma unroll
    for (int i = 0; i < 2; i++)
        #pragma unroll
        for (int j = 0; j < 8; j++)
            #pragma unroll
            for (int r = 0; r < 4; r++) acc[i][j][r] = 0.f;

    const int KT = K >> 6;

    #pragma unroll
    for (int p = 0; p < 2; p++) {
        const int k0 = p * 64;
        #pragma unroll
        for (int i = 0; i < 4; i++) {
            CP_ASYNC16(dA + p*GSTG_PAIR + i*32*GROWB, Agr + (size_t)(i*32)*K + k0);
            CP_ASYNC16(dB + p*GSTG_PAIR + i*32*GROWB, Bgr + (size_t)(i*32)*K + k0);
        }
        CP_COMMIT();
    }

    int s = 0, sl = 2;
    for (int it = 0; it < KT; it++) {
        CP_WAIT1();
        __syncthreads();

        if (it + 2 < KT) {
            const int k0 = (it + 2) * 64;
            const uint32_t so = (uint32_t)(sl * GSTG_PAIR);
            #pragma unroll
            for (int i = 0; i < 4; i++) {
                CP_ASYNC16(dA + so + i*32*GROWB, Agr + (size_t)(i*32)*K + k0);
                CP_ASYNC16(dB + so + i*32*GROWB, Bgr + (size_t)(i*32)*K + k0);
            }
        }
        CP_COMMIT();

        const uint32_t sbase = smb + (uint32_t)(s * GSTG_PAIR);
        #pragma unroll
        for (int ks = 0; ks < 4; ks++) {
            uint32_t a[2][4];
            #pragma unroll
            for (int mf = 0; mf < 2; mf++)
                ldsm_x4(a[mf][0], a[mf][1], a[mf][2], a[mf][3],
                        sbase + aoff + mf*(16*GROWB) + ks*32);
            #pragma unroll
            for (int p = 0; p < 4; p++) {
                uint32_t b0, b1, b2, b3;
                ldsm_x4(b0, b1, b2, b3, sbase + boff + p*(16*GROWB) + ks*32);
                #pragma unroll
                for (int mf = 0; mf < 2; mf++) {
                    mma_f16(acc[mf][2*p][0], acc[mf][2*p][1], acc[mf][2*p][2], acc[mf][2*p][3],
                            a[mf][0], a[mf][1], a[mf][2], a[mf][3], b0, b1);
                    mma_f16(acc[mf][2*p+1][0], acc[mf][2*p+1][1], acc[mf][2*p+1][2], acc[mf][2*p+1][3],
                            a[mf][0], a[mf][1], a[mf][2], a[mf][3], b2, b3);
                }
            }
        }

        s = (s + 1 == 3) ? 0 : s + 1;
        sl = (sl + 1 == 3) ? 0 : sl + 1;
    }

    #pragma unroll
    for (int mf = 0; mf < 2; mf++) {
        const int row0 = m0 + wm*32 + mf*16 + gq;
        const int bb = row0 / S_, ss = row0 % S_;
        #pragma unroll
        for (int nf = 0; nf < 8; nf++) {
            const int col = n0 + wn*64 + nf*8 + tr*2;
            const float b0 = bias[col], b1 = bias[col+1];
            const int dcol = col - n0;
            if (!vmode) {
                __half* C = (bx < 16) ? g_Q : g_K;
                __half* Cp0 = C + (((size_t)(bb*heads + nt))*S_ + ss)*HD_ + dcol;
                *(uint32_t*)Cp0           = pack_h2(acc[mf][nf][0] + b0, acc[mf][nf][1] + b1);
                *(uint32_t*)(Cp0 + 8*HD_) = pack_h2(acc[mf][nf][2] + b0, acc[mf][nf][3] + b1);
            } else {
                __half* base = g_Vt + (((size_t)(bb*G_ + nt))*HD_ + dcol)*S_ + ss;
                base[0]       = __float2half_rn(acc[mf][nf][0] + b0);
                base[S_]      = __float2half_rn(acc[mf][nf][1] + b1);
                base[8]       = __float2half_rn(acc[mf][nf][2] + b0);
                base[S_ + 8]  = __float2half_rn(acc[mf][nf][3] + b1);
            }
        }
    }
}

// ---------------------------------------------------------------------------
// O projection GEMM (unchanged)
// ---------------------------------------------------------------------------
__global__ __launch_bounds__(256, 2)
void o_gemm(const __half* __restrict__ A, const __half* __restrict__ Bw,
            const float* __restrict__ bias, float* __restrict__ C) {
    extern __shared__ __align__(16) unsigned char gsm[];
    const uint32_t smb = smem_u32(gsm);
    const int N = E_, K = E_;

    const int t    = threadIdx.x;
    const int lane = t & 31;
    const int wid  = t >> 5;
    const int wm   = wid & 3;
    const int wn   = wid >> 2;
    const int gq   = lane >> 2;
    const int tr   = lane & 3;
    const int lrow = lane & 7, lmat = lane >> 3;
    const int m0 = blockIdx.y * 128, n0 = blockIdx.x * 128;

    const int row8 = t >> 3, chk = t & 7;
    const __half* Agr = A  + (size_t)(m0 + row8) * K + chk*8;
    const __half* Bgr = Bw + (size_t)(n0 + row8) * K + chk*8;
    const uint32_t dA = smb + (uint32_t)(row8*GROWB + chk*16);
    const uint32_t dB = dA + GSTG_B;

    const uint32_t aoff = (uint32_t)(((wm*32 + (lmat&1)*8 + lrow)*GROW_H + (lmat>>1)*8) * 2);
    const uint32_t boff = (uint32_t)(((wn*64 + (lmat>>1)*8 + lrow)*GROW_H + (lmat&1)*8) * 2) + GSTG_B;

    float acc[2][8][4];
    #pragma unroll
    for (int i = 0; i < 2; i++)
        #pragma unroll
        for (int j = 0; j < 8; j++)
            #pragma unroll
            for (int r = 0; r < 4; r++) acc[i][j][r] = 0.f;

    const int KT = K >> 6;

    #pragma unroll
    for (int p = 0; p < 2; p++) {
        const int k0 = p * 64;
        #pragma unroll
        for (int i = 0; i < 4; i++) {
            CP_ASYNC16(dA + p*GSTG_PAIR + i*32*GROWB, Agr + (size_t)(i*32)*K + k0);
            CP_ASYNC16(dB + p*GSTG_PAIR + i*32*GROWB, Bgr + (size_t)(i*32)*K + k0);
        }
        CP_COMMIT();
    }

    int s = 0, sl = 2;
    for (int it = 0; it < KT; it++) {
        CP_WAIT1();
        __syncthreads();

        if (it + 2 < KT) {
            const int k0 = (it + 2) * 64;
            const uint32_t so = (uint32_t)(sl * GSTG_PAIR);
            #pragma unroll
            for (int i = 0; i < 4; i++) {
                CP_ASYNC16(dA + so + i*32*GROWB, Agr + (size_t)(i*32)*K + k0);
                CP_ASYNC16(dB + so + i*32*GROWB, Bgr + (size_t)(i*32)*K + k0);
            }
        }
        CP_COMMIT();

        const uint32_t sbase = smb + (uint32_t)(s * GSTG_PAIR);
        #pragma unroll
        for (int ks = 0; ks < 4; ks++) {
            uint32_t a[2][4];
            #pragma unroll
            for (int mf = 0; mf < 2; mf++)
                ldsm_x4(a[mf][0], a[mf][1], a[mf][2], a[mf][3],
                        sbase + aoff + mf*(16*GROWB) + ks*32);
            #pragma unroll
            for (int p = 0; p < 4; p++) {
                uint32_t b0, b1, b2, b3;
                ldsm_x4(b0, b1, b2, b3, sbase + boff + p*(16*GROWB) + ks*32);
                #pragma unroll
                for (int mf = 0; mf < 2; mf++) {
                    mma_f16(acc[mf][2*p][0], acc[mf][2*p][1], acc[mf][2*p][2], acc[mf][2*p][3],
                            a[mf][0], a[mf][1], a[mf][2], a[mf][3], b0, b1);
                    mma_f16(acc[mf][2*p+1][0], acc[mf][2*p+1][1], acc[mf][2*p+1][2], acc[mf][2*p+1][3],
                            a[mf][0], a[mf][1], a[mf][2], a[mf][3], b2, b3);
                }
            }
        }

        s = (s + 1 == 3) ? 0 : s + 1;
        sl = (sl + 1 == 3) ? 0 : sl + 1;
    }

    #pragma unroll
    for (int mf = 0; mf < 2; mf++) {
        const int row0 = m0 + wm*32 + mf*16 + gq;
        #pragma unroll
        for (int nf = 0; nf < 8; nf++) {
            const int col = n0 + wn*64 + nf*8 + tr*2;
            const float b0 = bias[col], b1 = bias[col+1];
            float* Cp0 = C + (size_t)row0 * N + col;
            float* Cp1 = Cp0 + (size_t)8 * N;
            *(float2*)Cp0 = make_float2(acc[mf][nf][0] + b0, acc[mf][nf][1] + b1);
            *(float2*)Cp1 = make_float2(acc[mf][nf][2] + b0, acc[mf][nf][3] + b1);
        }
    }
}

// ---------------------------------------------------------------------------
// Flash attention — R14: non-split, 3 CTAs/SM, f16x2 exp, conditional rescale
// ---------------------------------------------------------------------------
#define FKROW_H 136
#define FKROWB  272
#define FVROW_H 72
#define FVROWB  144
#define FKSTG_B (64*FKROWB)
#define FVSTG_B (128*FVROWB)
#define FLASH_SMEM (2*FKSTG_B + 2*FVSTG_B)   // 71680 (x3/SM = 215040)

__global__ __launch_bounds__(128, 3)
void flash_h(__half* __restrict__ O) {
    extern __shared__ __align__(16) unsigned char fsm[];
    const int t = threadIdx.x, lane = t & 31, w = t >> 5;
    const int gq = lane >> 2, tr = lane & 3;
    const int lrow = lane & 7, lmat = lane >> 3;
    const int qt = blockIdx.x, h = blockIdx.y, b = blockIdx.z;
    const int g  = h % G_;
    const int q0 = qt * 64;

    const __half* Qg  = g_Q  + (((size_t)(b*H_ + h))*S_ + q0) * HD_;
    const __half* Kg  = g_K  + (((size_t)(b*G_ + g))*S_) * HD_;
    const __half* Vtg = g_Vt + (((size_t)(b*G_ + g))*HD_) * S_;

    const uint32_t uK = smem_u32(fsm);
    const uint32_t uV = uK + 2*FKSTG_B;

    const int krow = t >> 4, kchk = t & 15;
    const int vrow = t >> 3, vchk = t & 7;

    const uint32_t koff = (uint32_t)((((lmat>>1)*8 + lrow)*FKROW_H + (lmat&1)*8) * 2);
    const uint32_t voff = (uint32_t)((((lmat>>1)*8 + lrow)*FVROW_H + (lmat&1)*8) * 2);

    // scale folded with log2(e): 1/sqrt(128) * log2(e)
    const float scale = 0.12751879523243977f;
    const int qrow = w*16 + gq;
    uint32_t qa[8][4];
    #pragma unroll
    for (int ks = 0; ks < 8; ks++) {
        const int c = ks*16 + tr*2;
        #pragma unroll
        for (int r = 0; r < 4; r++) {
            const int rr = qrow + (r & 1)*8;
            const int cc = c + (r >> 1)*8;
            const uint32_t u = *(const uint32_t*)(Qg + (size_t)rr*HD_ + cc);
            const __half2 hv = *reinterpret_cast<const __half2*>(&u);
            const float2 f = __half22float2(hv);
            qa[ks][r] = pack_h2(f.x*scale, f.y*scale);
        }
    }

    float oc[16][4];
    #pragma unroll
    for (int jf = 0; jf < 16; jf++)
        #pragma unroll
        for (int r = 0; r < 4; r++) oc[jf][r] = 0.f;
    float m0 = -1e30f, m1 = -1e30f, l0 = 0.f, l1 = 0.f;

    #pragma unroll
    for (int i = 0; i < 8; i++)
        CP_ASYNC16(uK + (uint32_t)((krow + 8*i)*FKROWB + kchk*16),
                   Kg + (size_t)(krow + 8*i)*HD_ + kchk*8);
    #pragma unroll
    for (int i = 0; i < 8; i++)
        CP_ASYNC16(uV + (uint32_t)((vrow + 16*i)*FVROWB + vchk*16),
                   Vtg + (size_t)(vrow + 16*i)*S_ + vchk*8);
    CP_COMMIT();

    const unsigned long long* mrow0p = g_MB + ((size_t)(b*S_ + q0 + w*16 + gq)) * 32;
    const unsigned long long* mrow1p = mrow0p + 8*32;

    for (int kt = 0; kt < S_/64; kt++) {
        __syncthreads();
        if (kt + 1 < S_/64) {
            const uint32_t so = ((kt+1) & 1);
            const size_t kvo = (size_t)(kt+1) * 64;
            #pragma unroll
            for (int i = 0; i < 8; i++)
                CP_ASYNC16(uK + so*FKSTG_B + (uint32_t)((krow + 8*i)*FKROWB + kchk*16),
                           Kg + (kvo + krow + 8*i)*HD_ + kchk*8);
            #pragma unroll
            for (int i = 0; i < 8; i++)
                CP_ASYNC16(uV + so*FVSTG_B + (uint32_t)((vrow + 16*i)*FVROWB + vchk*16),
                           Vtg + (size_t)(vrow + 16*i)*S_ + kvo + vchk*8);
        }
        CP_COMMIT();
        CP_WAIT1();
        __syncthreads();

        const uint32_t uKst = uK + (kt & 1)*FKSTG_B;
        const uint32_t uVst = uV + (kt & 1)*FVSTG_B;

        // ---- scores (base-2 domain) ----
        float sc[8][4];
        #pragma unroll
        for (int j = 0; j < 8; j++)
            #pragma unroll
            for (int r = 0; r < 4; r++) sc[j][r] = 0.f;
        #pragma unroll
        for (int ks = 0; ks < 8; ks++) {
            #pragma unroll
            for (int p = 0; p < 4; p++) {
                uint32_t b0, b1, b2, b3;
                ldsm_x4(b0, b1, b2, b3, uKst + koff + p*(16*FKROWB) + ks*32);
                mma_f16(sc[2*p][0], sc[2*p][1], sc[2*p][2], sc[2*p][3],
                        qa[ks][0], qa[ks][1], qa[ks][2], qa[ks][3], b0, b1);
                mma_f16(sc[2*p+1][0], sc[2*p+1][1], sc[2*p+1][2], sc[2*p+1][3],
                        qa[ks][0], qa[ks][1], qa[ks][2], qa[ks][3], b2, b3);
            }
        }

        // ---- mask + row max ----
        const unsigned long long mb0 = mrow0p[kt];
        const unsigned long long mb1 = mrow1p[kt];
        float mx0 = -1e30f, mx1 = -1e30f;
        #pragma unroll
        for (int j = 0; j < 8; j++) {
            const int pos = tr*2 + j*8;
            if (!((mb0 >> pos) & 1ULL))       sc[j][0] = -10000.f;
            if (!((mb0 >> (pos+1)) & 1ULL))   sc[j][1] = -10000.f;
            if (!((mb1 >> pos) & 1ULL))       sc[j][2] = -10000.f;
            if (!((mb1 >> (pos+1)) & 1ULL))   sc[j][3] = -10000.f;
            mx0 = fmaxf(mx0, fmaxf(sc[j][0], sc[j][1]));
            mx1 = fmaxf(mx1, fmaxf(sc[j][2], sc[j][3]));
        }
        mx0 = fmaxf(mx0, __shfl_xor_sync(0xffffffffu, mx0, 1));
        mx0 = fmaxf(mx0, __shfl_xor_sync(0xffffffffu, mx0, 2));
        mx1 = fmaxf(mx1, __shfl_xor_sync(0xffffffffu, mx1, 1));
        mx1 = fmaxf(mx1, __shfl_xor_sync(0xffffffffu, mx1, 2));

        const float mn0 = fmaxf(m0, mx0), mn1 = fmaxf(m1, mx1);
        const float f0 = exp2f(m0 - mn0), f1 = exp2f(m1 - mn1);
        m0 = mn0; m1 = mn1;

        // ---- P = exp2 via f16x2 MUFU; results ARE the PV A-fragments ----
        uint32_t ph0[8], ph1[8];
        float s0 = 0.f, s1 = 0.f;
        #pragma unroll
        for (int j = 0; j < 8; j++) {
            ph0[j] = ex2_h2(pack_h2(sc[j][0] - mn0, sc[j][1] - mn0));
            ph1[j] = ex2_h2(pack_h2(sc[j][2] - mn1, sc[j][3] - mn1));
            const float2 p0 = __half22float2(*reinterpret_cast<__half2*>(&ph0[j]));
            const float2 p1 = __half22float2(*reinterpret_cast<__half2*>(&ph1[j]));
            s0 += p0.x + p0.y;
            s1 += p1.x + p1.y;
        }
        s0 += __shfl_xor_sync(0xffffffffu, s0, 1);
        s0 += __shfl_xor_sync(0xffffffffu, s0, 2);
        s1 += __shfl_xor_sync(0xffffffffu, s1, 1);
        s1 += __shfl_xor_sync(0xffffffffu, s1, 2);
        l0 = l0 * f0 + s0;
        l1 = l1 * f1 + s1;

        // ---- conditional rescale (skip when running max unchanged) ----
        if (__ballot_sync(0xffffffffu, (f0 < 1.f) || (f1 < 1.f))) {
            #pragma unroll
            for (int jf = 0; jf < 16; jf++) {
                oc[jf][0] *= f0; oc[jf][1] *= f0;
                oc[jf][2] *= f1; oc[jf][3] *= f1;
            }
        }

        // ---- PV ----
        #pragma unroll
        for (int ks = 0; ks < 4; ks++) {
            const uint32_t a0 = ph0[2*ks];
            const uint32_t a1 = ph1[2*ks];
            const uint32_t a2 = ph0[2*ks+1];
            const uint32_t a3 = ph1[2*ks+1];
            #pragma unroll
            for (int p = 0; p < 8; p++) {
                uint32_t b0, b1, b2, b3;
                ldsm_x4(b0, b1, b2, b3, uVst + voff + p*(16*FVROWB) + ks*32);
                mma_f16(oc[2*p][0], oc[2*p][1], oc[2*p][2], oc[2*p][3],
                        a0, a1, a2, a3, b0, b1);
                mma_f16(oc[2*p+1][0], oc[2*p+1][1], oc[2*p+1][2], oc[2*p+1][3],
                        a0, a1, a2, a3, b2, b3);
            }
        }
    }

    const float inv0 = 1.f / l0, inv1 = 1.f / l1;
    __half* O0 = O + ((size_t)(b*S_ + q0 + w*16 + gq)) * E_ + h*HD_;
    __half* O1 = O0 + (size_t)8 * E_;
    #pragma unroll
    for (int jf = 0; jf < 16; jf++) {
        const int c = jf*8 + tr*2;
        *(uint32_t*)(O0 + c) = pack_h2(oc[jf][0]*inv0, oc[jf][1]*inv0);
        *(uint32_t*)(O1 + c) = pack_h2(oc[jf][2]*inv1, oc[jf][3]*inv1);
    }
}

// ---------------------------------------------------------------------------
extern "C" void kernel_launch(void* const* d_in, const int* in_sizes, int n_in,
                              void* d_out, int out_size) {
    const float* x  = (const float*)d_in[0];
    const int* mask = (const int*)  d_in[1];
    const float* Wq = (const float*)d_in[2];
    const float* bq = (const float*)d_in[3];
    const float* Wk = (const float*)d_in[4];
    const float* bk = (const float*)d_in[5];
    const float* Wv = (const float*)d_in[6];
    const float* bv = (const float*)d_in[7];
    const float* Wo = (const float*)d_in[8];
    const float* bo = (const float*)d_in[9];
    float* out = (float*)d_out;

    __half *Od, *WoT, *Xr;
    cudaGetSymbolAddress((void**)&Od,  g_O);
    cudaGetSymbolAddress((void**)&WoT, g_WoT);
    cudaGetSymbolAddress((void**)&Xr,  g_Xr);

    cudaFuncSetAttribute(flash_h,  cudaFuncAttributeMaxDynamicSharedMemorySize, FLASH_SMEM);
    cudaFuncSetAttribute(qkv_gemm, cudaFuncAttributeMaxDynamicSharedMemorySize, GEMM_SMEM);
    cudaFuncSetAttribute(o_gemm,   cudaFuncAttributeMaxDynamicSharedMemorySize, GEMM_SMEM);

    // prep
    prep_w<<<dim3(64, 64, 4), dim3(32, 8)>>>(Wq, Wk, Wv, Wo);
    f2h_copy<<<MTOT*E_/2/256, 256>>>(x, Xr);
    mask_pack<<<(int)((size_t)B_*S_*S_/256), 256>>>(mask);

    // fused Q/K/V projections (V written transposed)
    qkv_gemm<<<dim3(24, MTOT/128), 256, GEMM_SMEM>>>(bq, bk, bv);

    // attention (3 CTAs/SM)
    flash_h<<<dim3(S_/64, H_, B_), 128, FLASH_SMEM>>>(Od);

    // output projection
    o_gemm<<<dim3(E_/128, MTOT/128), 256, GEMM_SMEM>>>(Od, WoT, bo, out);
}

// round 15
// speedup vs baseline: 1.0295x; 1.0295x over previous
#include <cuda_runtime.h>
#include <cuda_fp16.h>
#include <math.h>
#include <stdint.h>

#define B_  2
#define S_  2048
#define E_  2048
#define H_  16
#define G_  4
#define HD_ 128
#define GD_ 512
#define MTOT (B_*S_)

// ---------------- device scratch (allocation-free rule) ----------------
__device__ __half g_Q [(size_t)B_*H_*S_*HD_];
__device__ __half g_K [(size_t)B_*G_*S_*HD_];
__device__ __half g_Vt[(size_t)B_*G_*HD_*S_];
__device__ __half g_O [(size_t)B_*S_*E_];
__device__ __half g_Xr[(size_t)B_*S_*E_];
__device__ __half g_WqT[(size_t)E_*E_];
__device__ __half g_WkT[(size_t)GD_*E_];
__device__ __half g_WvT[(size_t)GD_*E_];
__device__ __half g_WoT[(size_t)E_*E_];
__device__ unsigned long long g_MB[(size_t)B_*S_*32];

// ---------------- helpers ----------------
__device__ __forceinline__ uint32_t smem_u32(const void* p) {
    uint32_t a;
    asm("{ .reg .u64 t; cvta.to.shared.u64 t, %1; cvt.u32.u64 %0, t; }" : "=r"(a) : "l"(p));
    return a;
}
__device__ __forceinline__ uint32_t pack_h2(float lo, float hi) {
    __half2 v = __floats2half2_rn(lo, hi);
    return *reinterpret_cast<uint32_t*>(&v);
}

#define CP_ASYNC16(dst, src) \
    asm volatile("cp.async.cg.shared.global [%0], [%1], 16;" :: "r"(dst), "l"(src) : "memory")
#define CP_COMMIT() asm volatile("cp.async.commit_group;" ::: "memory")
#define CP_WAIT1()  asm volatile("cp.async.wait_group 1;"  ::: "memory")

__device__ __forceinline__ void mma_f16(float& d0, float& d1, float& d2, float& d3,
                                        uint32_t a0, uint32_t a1, uint32_t a2, uint32_t a3,
                                        uint32_t b0, uint32_t b1) {
    asm volatile("mma.sync.aligned.m16n8k16.row.col.f32.f16.f16.f32 "
                 "{%0,%1,%2,%3},{%4,%5,%6,%7},{%8,%9},{%0,%1,%2,%3};"
                 : "+f"(d0), "+f"(d1), "+f"(d2), "+f"(d3)
                 : "r"(a0), "r"(a1), "r"(a2), "r"(a3), "r"(b0), "r"(b1));
}
__device__ __forceinline__ void ldsm_x4(uint32_t& r0, uint32_t& r1, uint32_t& r2, uint32_t& r3,
                                        uint32_t addr) {
    asm volatile("ldmatrix.sync.aligned.m8n8.x4.shared.b16 {%0,%1,%2,%3}, [%4];"
                 : "=r"(r0), "=r"(r1), "=r"(r2), "=r"(r3) : "r"(addr));
}

// ---------------------------------------------------------------------------
// Prep kernels
// ---------------------------------------------------------------------------
__global__ void prep_w(const float* __restrict__ Wq, const float* __restrict__ Wk,
                       const float* __restrict__ Wv, const float* __restrict__ Wo) {
    __shared__ float tt[32][33];
    const int z = blockIdx.z;
    const int tx = threadIdx.x, ty = threadIdx.y;
    const float* in; __half* out; int Cc;
    if      (z == 0) { in = Wq; out = g_WqT; Cc = E_;  }
    else if (z == 1) { in = Wk; out = g_WkT; Cc = GD_; }
    else if (z == 2) { in = Wv; out = g_WvT; Cc = GD_; }
    else             { in = Wo; out = g_WoT; Cc = E_;  }
    const int c0 = blockIdx.x * 32, r0 = blockIdx.y * 32;
    if (c0 >= Cc) return;
    #pragma unroll
    for (int i = ty; i < 32; i += 8)
        tt[i][tx] = in[(size_t)(r0 + i) * Cc + c0 + tx];
    __syncthreads();
    #pragma unroll
    for (int i = ty; i < 32; i += 8)
        out[(size_t)(c0 + i) * E_ + r0 + tx] = __float2half_rn(tt[tx][i]);
}

__global__ void f2h_copy(const float* __restrict__ in, __half* __restrict__ out) {
    const size_t i = (size_t)blockIdx.x * 256 + threadIdx.x;
    float2 v = *(const float2*)(in + 2*i);
    *(uint32_t*)(out + 2*i) = pack_h2(v.x, v.y);
}

__global__ void mask_pack(const int* __restrict__ mask) {
    const size_t i = (size_t)blockIdx.x * 256 + threadIdx.x;
    const unsigned v = (mask[i] != 0) ? 1u : 0u;
    const unsigned bal = __ballot_sync(0xffffffffu, v);
    if ((threadIdx.x & 31) == 0)
        ((uint32_t*)g_MB)[i >> 5] = bal;
}

// ---------------------------------------------------------------------------
// Fused QKV GEMM (best config, unchanged from R12)
// ---------------------------------------------------------------------------
#define GROW_H 72
#define GROWB  144
#define GSTG_B (128*GROW_H*2)
#define GSTG_PAIR (2*GSTG_B)
#define GEMM_SMEM (3*GSTG_PAIR)      // 110592

__global__ __launch_bounds__(256, 2)
void qkv_gemm(const float* __restrict__ bq, const float* __restrict__ bk,
              const float* __restrict__ bv) {
    extern __shared__ __align__(16) unsigned char gsm[];
    const uint32_t smb = smem_u32(gsm);

    const int t    = threadIdx.x;
    const int lane = t & 31;
    const int wid  = t >> 5;
    const int wm   = wid & 3;
    const int wn   = wid >> 2;
    const int gq   = lane >> 2;
    const int tr   = lane & 3;
    const int lrow = lane & 7, lmat = lane >> 3;
    const int bx = blockIdx.x;
    const int m0 = blockIdx.y * 128;

    const __half* Bw; const float* bias; int nt, heads, vmode;
    if (bx < 16)      { Bw = g_WqT; bias = bq; nt = bx;      heads = 16; vmode = 0; }
    else if (bx < 20) { Bw = g_WkT; bias = bk; nt = bx - 16; heads = 4;  vmode = 0; }
    else              { Bw = g_WvT; bias = bv; nt = bx - 20; heads = 4;  vmode = 1; }
    const int n0 = nt * 128;
    const int K = E_;

    const int row8 = t >> 3, chk = t & 7;
    const __half* Agr = g_Xr + (size_t)(m0 + row8) * K + chk*8;
    const __half* Bgr = Bw   + (size_t)(n0 + row8) * K + chk*8;
    const uint32_t dA = smb + (uint32_t)(row8*GROWB + chk*16);
    const uint32_t dB = dA + GSTG_B;

    const uint32_t aoff = (uint32_t)(((wm*32 + (lmat&1)*8 + lrow)*GROW_H + (lmat>>1)*8) * 2);
    const uint32_t boff = (uint32_t)(((wn*64 + (lmat>>1)*8 + lrow)*GROW_H + (lmat&1)*8) * 2) + GSTG_B;

    float acc[2][8][4];
    #pragma unroll
    for (int i = 0; i < 2; i++)
        #pragma unroll
        for (int j = 0; j < 8; j++)
            #pragma unroll
            for (int r = 0; r < 4; r++) acc[i][j][r] = 0.f;

    const int KT = K >> 6;

    #pragma unroll
    for (int p = 0; p < 2; p++) {
        const int k0 = p * 64;
        #pragma unroll
        for (int i = 0; i < 4; i++) {
            CP_ASYNC16(dA + p*GSTG_PAIR + i*32*GROWB, Agr + (size_t)(i*32)*K + k0);
            CP_ASYNC16(dB + p*GSTG_PAIR + i*32*GROWB, Bgr + (size_t)(i*32)*K + k0);
        }
        CP_COMMIT();
    }

    int s = 0, sl = 2;
    for (int it = 0; it < KT; it++) {
        CP_WAIT1();
        __syncthreads();

        if (it + 2 < KT) {
            const int k0 = (it + 2) * 64;
            const uint32_t so = (uint32_t)(sl * GSTG_PAIR);
            #pragma unroll
            for (int i = 0; i < 4; i++) {
                CP_ASYNC16(dA + so + i*32*GROWB, Agr + (size_t)(i*32)*K + k0);
                CP_ASYNC16(dB + so + i*32*GROWB, Bgr + (size_t)(i*32)*K + k0);
            }
        }
        CP_COMMIT();

        const uint32_t sbase = smb + (uint32_t)(s * GSTG_PAIR);
        #pragma unroll
        for (int ks = 0; ks < 4; ks++) {
            uint32_t a[2][4];
            #pragma unroll
            for (int mf = 0; mf < 2; mf++)
                ldsm_x4(a[mf][0], a[mf][1], a[mf][2], a[mf][3],
                        sbase + aoff + mf*(16*GROWB) + ks*32);
            #pragma unroll
            for (int p = 0; p < 4; p++) {
                uint32_t b0, b1, b2, b3;
                ldsm_x4(b0, b1, b2, b3, sbase + boff + p*(16*GROWB) + ks*32);
                #pragma unroll
                for (int mf = 0; mf < 2; mf++) {
                    mma_f16(acc[mf][2*p][0], acc[mf][2*p][1], acc[mf][2*p][2], acc[mf][2*p][3],
                            a[mf][0], a[mf][1], a[mf][2], a[mf][3], b0, b1);
                    mma_f16(acc[mf][2*p+1][0], acc[mf][2*p+1][1], acc[mf][2*p+1][2], acc[mf][2*p+1][3],
                            a[mf][0], a[mf][1], a[mf][2], a[mf][3], b2, b3);
                }
            }
        }

        s = (s + 1 == 3) ? 0 : s + 1;
        sl = (sl + 1 == 3) ? 0 : sl + 1;
    }

    #pragma unroll
    for (int mf = 0; mf < 2; mf++) {
        const int row0 = m0 + wm*32 + mf*16 + gq;
        const int bb = row0 / S_, ss = row0 % S_;
        #pragma unroll
        for (int nf = 0; nf < 8; nf++) {
            const int col = n0 + wn*64 + nf*8 + tr*2;
            const float b0 = bias[col], b1 = bias[col+1];
            const int dcol = col - n0;
            if (!vmode) {
                __half* C = (bx < 16) ? g_Q : g_K;
                __half* Cp0 = C + (((size_t)(bb*heads + nt))*S_ + ss)*HD_ + dcol;
                *(uint32_t*)Cp0           = pack_h2(acc[mf][nf][0] + b0, acc[mf][nf][1] + b1);
                *(uint32_t*)(Cp0 + 8*HD_) = pack_h2(acc[mf][nf][2] + b0, acc[mf][nf][3] + b1);
            } else {
                __half* base = g_Vt + (((size_t)(bb*G_ + nt))*HD_ + dcol)*S_ + ss;
                base[0]       = __float2half_rn(acc[mf][nf][0] + b0);
                base[S_]      = __float2half_rn(acc[mf][nf][1] + b1);
                base[8]       = __float2half_rn(acc[mf][nf][2] + b0);
                base[S_ + 8]  = __float2half_rn(acc[mf][nf][3] + b1);
            }
        }
    }
}

// ---------------------------------------------------------------------------
// O projection GEMM (unchanged from R12)
// ---------------------------------------------------------------------------
__global__ __launch_bounds__(256, 2)
void o_gemm(const __half* __restrict__ A, const __half* __restrict__ Bw,
            const float* __restrict__ bias, float* __restrict__ C) {
    extern __shared__ __align__(16) unsigned char gsm[];
    const uint32_t smb = smem_u32(gsm);
    const int N = E_, K = E_;

    const int t    = threadIdx.x;
    const int lane = t & 31;
    const int wid  = t >> 5;
    const int wm   = wid & 3;
    const int wn   = wid >> 2;
    const int gq   = lane >> 2;
    const int tr   = lane & 3;
    const int lrow = lane & 7, lmat = lane >> 3;
    const int m0 = blockIdx.y * 128, n0 = blockIdx.x * 128;

    const int row8 = t >> 3, chk = t & 7;
    const __half* Agr = A  + (size_t)(m0 + row8) * K + chk*8;
    const __half* Bgr = Bw + (size_t)(n0 + row8) * K + chk*8;
    const uint32_t dA = smb + (uint32_t)(row8*GROWB + chk*16);
    const uint32_t dB = dA + GSTG_B;

    const uint32_t aoff = (uint32_t)(((wm*32 + (lmat&1)*8 + lrow)*GROW_H + (lmat>>1)*8) * 2);
    const uint32_t boff = (uint32_t)(((wn*64 + (lmat>>1)*8 + lrow)*GROW_H + (lmat&1)*8) * 2) + GSTG_B;

    float acc[2][8][4];
    #pragma unroll
    for (int i = 0; i < 2; i++)
        #pragma unroll
        for (int j = 0; j < 8; j++)
            #pragma unroll
            for (int r = 0; r < 4; r++) acc[i][j][r] = 0.f;

    const int KT = K >> 6;

    #pragma unroll
    for (int p = 0; p < 2; p++) {
        const int k0 = p * 64;
        #pragma unroll
        for (int i = 0; i < 4; i++) {
            CP_ASYNC16(dA + p*GSTG_PAIR + i*32*GROWB, Agr + (size_t)(i*32)*K + k0);
            CP_ASYNC16(dB + p*GSTG_PAIR + i*32*GROWB, Bgr + (size_t)(i*32)*K + k0);
        }
        CP_COMMIT();
    }

    int s = 0, sl = 2;
    for (int it = 0; it < KT; it++) {
        CP_WAIT1();
        __syncthreads();

        if (it + 2 < KT) {
            const int k0 = (it + 2) * 64;
            const uint32_t so = (uint32_t)(sl * GSTG_PAIR);
            #pragma unroll
            for (int i = 0; i < 4; i++) {
                CP_ASYNC16(dA + so + i*32*GROWB, Agr + (size_t)(i*32)*K + k0);
                CP_ASYNC16(dB + so + i*32*GROWB, Bgr + (size_t)(i*32)*K + k0);
            }
        }
        CP_COMMIT();

        const uint32_t sbase = smb + (uint32_t)(s * GSTG_PAIR);
        #pragma unroll
        for (int ks = 0; ks < 4; ks++) {
            uint32_t a[2][4];
            #pragma unroll
            for (int mf = 0; mf < 2; mf++)
                ldsm_x4(a[mf][0], a[mf][1], a[mf][2], a[mf][3],
                        sbase + aoff + mf*(16*GROWB) + ks*32);
            #pragma unroll
            for (int p = 0; p < 4; p++) {
                uint32_t b0, b1, b2, b3;
                ldsm_x4(b0, b1, b2, b3, sbase + boff + p*(16*GROWB) + ks*32);
                #pragma unroll
                for (int mf = 0; mf < 2; mf++) {
                    mma_f16(acc[mf][2*p][0], acc[mf][2*p][1], acc[mf][2*p][2], acc[mf][2*p][3],
                            a[mf][0], a[mf][1], a[mf][2], a[mf][3], b0, b1);
                    mma_f16(acc[mf][2*p+1][0], acc[mf][2*p+1][1], acc[mf][2*p+1][2], acc[mf][2*p+1][3],
                            a[mf][0], a[mf][1], a[mf][2], a[mf][3], b2, b3);
                }
            }
        }

        s = (s + 1 == 3) ? 0 : s + 1;
        sl = (sl + 1 == 3) ? 0 : sl + 1;
    }

    #pragma unroll
    for (int mf = 0; mf < 2; mf++) {
        const int row0 = m0 + wm*32 + mf*16 + gq;
        #pragma unroll
        for (int nf = 0; nf < 8; nf++) {
            const int col = n0 + wn*64 + nf*8 + tr*2;
            const float b0 = bias[col], b1 = bias[col+1];
            float* Cp0 = C + (size_t)row0 * N + col;
            float* Cp1 = Cp0 + (size_t)8 * N;
            *(float2*)Cp0 = make_float2(acc[mf][nf][0] + b0, acc[mf][nf][1] + b1);
            *(float2*)Cp1 = make_float2(acc[mf][nf][2] + b0, acc[mf][nf][3] + b1);
        }
    }
}

// ---------------------------------------------------------------------------
// Flash attention — R12 structure exactly; only change: exp2f with folded scale
// ---------------------------------------------------------------------------
#define FKROW_H 136
#define FKROWB  272
#define FVROW_H 72
#define FVROWB  144
#define FKSTG_B (64*FKROWB)
#define FVSTG_B (128*FVROWB)
#define FLASH_SMEM (2*FKSTG_B + 2*FVSTG_B)   // 71680 (x3/SM = 215040)

__global__ __launch_bounds__(128, 3)
void flash_h(__half* __restrict__ O) {
    extern __shared__ __align__(16) unsigned char fsm[];
    const int t = threadIdx.x, lane = t & 31, w = t >> 5;
    const int gq = lane >> 2, tr = lane & 3;
    const int lrow = lane & 7, lmat = lane >> 3;
    const int qt = blockIdx.x, h = blockIdx.y, b = blockIdx.z;
    const int g  = h % G_;
    const int q0 = qt * 64;

    const __half* Qg  = g_Q  + (((size_t)(b*H_ + h))*S_ + q0) * HD_;
    const __half* Kg  = g_K  + (((size_t)(b*G_ + g))*S_) * HD_;
    const __half* Vtg = g_Vt + (((size_t)(b*G_ + g))*HD_) * S_;

    const uint32_t uK = smem_u32(fsm);
    const uint32_t uV = uK + 2*FKSTG_B;

    const int krow = t >> 4, kchk = t & 15;
    const int vrow = t >> 3, vchk = t & 7;

    const uint32_t koff = (uint32_t)((((lmat>>1)*8 + lrow)*FKROW_H + (lmat&1)*8) * 2);
    const uint32_t voff = (uint32_t)((((lmat>>1)*8 + lrow)*FVROW_H + (lmat&1)*8) * 2);

    // 1/sqrt(128) * log2(e): softmax runs in base-2 domain
    const float scale = 0.12751879523243977f;
    const int qrow = w*16 + gq;
    uint32_t qa[8][4];
    #pragma unroll
    for (int ks = 0; ks < 8; ks++) {
        const int c = ks*16 + tr*2;
        #pragma unroll
        for (int r = 0; r < 4; r++) {
            const int rr = qrow + (r & 1)*8;
            const int cc = c + (r >> 1)*8;
            const uint32_t u = *(const uint32_t*)(Qg + (size_t)rr*HD_ + cc);
            const __half2 hv = *reinterpret_cast<const __half2*>(&u);
            const float2 f = __half22float2(hv);
            qa[ks][r] = pack_h2(f.x*scale, f.y*scale);
        }
    }

    float oc[16][4];
    #pragma unroll
    for (int jf = 0; jf < 16; jf++)
        #pragma unroll
        for (int r = 0; r < 4; r++) oc[jf][r] = 0.f;
    float m0 = -1e30f, m1 = -1e30f, l0 = 0.f, l1 = 0.f;

    #pragma unroll
    for (int i = 0; i < 8; i++)
        CP_ASYNC16(uK + (uint32_t)((krow + 8*i)*FKROWB + kchk*16),
                   Kg + (size_t)(krow + 8*i)*HD_ + kchk*8);
    #pragma unroll
    for (int i = 0; i < 8; i++)
        CP_ASYNC16(uV + (uint32_t)((vrow + 16*i)*FVROWB + vchk*16),
                   Vtg + (size_t)(vrow + 16*i)*S_ + vchk*8);
    CP_COMMIT();

    const unsigned long long* mrow0p = g_MB + ((size_t)(b*S_ + q0 + w*16 + gq)) * 32;
    const unsigned long long* mrow1p = mrow0p + 8*32;

    for (int kt = 0; kt < S_/64; kt++) {
        __syncthreads();
        if (kt + 1 < S_/64) {
            const uint32_t so = ((kt+1) & 1);
            const size_t kvo = (size_t)(kt+1) * 64;
            #pragma unroll
            for (int i = 0; i < 8; i++)
                CP_ASYNC16(uK + so*FKSTG_B + (uint32_t)((krow + 8*i)*FKROWB + kchk*16),
                           Kg + (kvo + krow + 8*i)*HD_ + kchk*8);
            #pragma unroll
            for (int i = 0; i < 8; i++)
                CP_ASYNC16(uV + so*FVSTG_B + (uint32_t)((vrow + 16*i)*FVROWB + vchk*16),
                           Vtg + (size_t)(vrow + 16*i)*S_ + kvo + vchk*8);
        }
        CP_COMMIT();
        CP_WAIT1();
        __syncthreads();

        const uint32_t uKst = uK + (kt & 1)*FKSTG_B;
        const uint32_t uVst = uV + (kt & 1)*FVSTG_B;

        float sc[8][4];
        #pragma unroll
        for (int j = 0; j < 8; j++)
            #pragma unroll
            for (int r = 0; r < 4; r++) sc[j][r] = 0.f;
        #pragma unroll
        for (int ks = 0; ks < 8; ks++) {
            #pragma unroll
            for (int p = 0; p < 4; p++) {
                uint32_t b0, b1, b2, b3;
                ldsm_x4(b0, b1, b2, b3, uKst + koff + p*(16*FKROWB) + ks*32);
                mma_f16(sc[2*p][0], sc[2*p][1], sc[2*p][2], sc[2*p][3],
                        qa[ks][0], qa[ks][1], qa[ks][2], qa[ks][3], b0, b1);
                mma_f16(sc[2*p+1][0], sc[2*p+1][1], sc[2*p+1][2], sc[2*p+1][3],
                        qa[ks][0], qa[ks][1], qa[ks][2], qa[ks][3], b2, b3);
            }
        }

        const unsigned long long mb0 = mrow0p[kt];
        const unsigned long long mb1 = mrow1p[kt];
        float mx0 = -1e30f, mx1 = -1e30f;
        #pragma unroll
        for (int j = 0; j < 8; j++) {
            const int pos = tr*2 + j*8;
            if (!((mb0 >> pos) & 1ULL))       sc[j][0] = -10000.f;
            if (!((mb0 >> (pos+1)) & 1ULL))   sc[j][1] = -10000.f;
            if (!((mb1 >> pos) & 1ULL))       sc[j][2] = -10000.f;
            if (!((mb1 >> (pos+1)) & 1ULL))   sc[j][3] = -10000.f;
            mx0 = fmaxf(mx0, fmaxf(sc[j][0], sc[j][1]));
            mx1 = fmaxf(mx1, fmaxf(sc[j][2], sc[j][3]));
        }
        mx0 = fmaxf(mx0, __shfl_xor_sync(0xffffffffu, mx0, 1));
        mx0 = fmaxf(mx0, __shfl_xor_sync(0xffffffffu, mx0, 2));
        mx1 = fmaxf(mx1, __shfl_xor_sync(0xffffffffu, mx1, 1));
        mx1 = fmaxf(mx1, __shfl_xor_sync(0xffffffffu, mx1, 2));

        const float mn0 = fmaxf(m0, mx0), mn1 = fmaxf(m1, mx1);
        const float f0 = exp2f(m0 - mn0), f1 = exp2f(m1 - mn1);
        m0 = mn0; m1 = mn1;

        float s0 = 0.f, s1 = 0.f;
        #pragma unroll
        for (int j = 0; j < 8; j++) {
            sc[j][0] = exp2f(sc[j][0] - mn0); s0 += sc[j][0];
            sc[j][1] = exp2f(sc[j][1] - mn0); s0 += sc[j][1];
            sc[j][2] = exp2f(sc[j][2] - mn1); s1 += sc[j][2];
            sc[j][3] = exp2f(sc[j][3] - mn1); s1 += sc[j][3];
        }
        s0 += __shfl_xor_sync(0xffffffffu, s0, 1);
        s0 += __shfl_xor_sync(0xffffffffu, s0, 2);
        s1 += __shfl_xor_sync(0xffffffffu, s1, 1);
        s1 += __shfl_xor_sync(0xffffffffu, s1, 2);
        l0 = l0 * f0 + s0;
        l1 = l1 * f1 + s1;

        #pragma unroll
        for (int jf = 0; jf < 16; jf++) {
            oc[jf][0] *= f0; oc[jf][1] *= f0;
            oc[jf][2] *= f1; oc[jf][3] *= f1;
        }

        #pragma unroll
        for (int ks = 0; ks < 4; ks++) {
            const uint32_t a0 = pack_h2(sc[2*ks][0],   sc[2*ks][1]);
            const uint32_t a1 = pack_h2(sc[2*ks][2],   sc[2*ks][3]);
            const uint32_t a2 = pack_h2(sc[2*ks+1][0], sc[2*ks+1][1]);
            const uint32_t a3 = pack_h2(sc[2*ks+1][2], sc[2*ks+1][3]);
            #pragma unroll
            for (int p = 0; p < 8; p++) {
                uint32_t b0, b1, b2, b3;
                ldsm_x4(b0, b1, b2, b3, uVst + voff + p*(16*FVROWB) + ks*32);
                mma_f16(oc[2*p][0], oc[2*p][1], oc[2*p][2], oc[2*p][3],
                        a0, a1, a2, a3, b0, b1);
                mma_f16(oc[2*p+1][0], oc[2*p+1][1], oc[2*p+1][2], oc[2*p+1][3],
                        a0, a1, a2, a3, b2, b3);
            }
        }
    }

    const float inv0 = 1.f / l0, inv1 = 1.f / l1;
    __half* O0 = O + ((size_t)(b*S_ + q0 + w*16 + gq)) * E_ + h*HD_;
    __half* O1 = O0 + (size_t)8 * E_;
    #pragma unroll
    for (int jf = 0; jf < 16; jf++) {
        const int c = jf*8 + tr*2;
        *(uint32_t*)(O0 + c) = pack_h2(oc[jf][0]*inv0, oc[jf][1]*inv0);
        *(uint32_t*)(O1 + c) = pack_h2(oc[jf][2]*inv1, oc[jf][3]*inv1);
    }
}

// ---------------------------------------------------------------------------
extern "C" void kernel_launch(void* const* d_in, const int* in_sizes, int n_in,
                              void* d_out, int out_size) {
    const float* x  = (const float*)d_in[0];
    const int* mask = (const int*)  d_in[1];
    const float* Wq = (const float*)d_in[2];
    const float* bq = (const float*)d_in[3];
    const float* Wk = (const float*)d_in[4];
    const float* bk = (const float*)d_in[5];
    const float* Wv = (const float*)d_in[6];
    const float* bv = (const float*)d_in[7];
    const float* Wo = (const float*)d_in[8];
    const float* bo = (const float*)d_in[9];
    float* out = (float*)d_out;

    __half *Od, *WoT, *Xr;
    cudaGetSymbolAddress((void**)&Od,  g_O);
    cudaGetSymbolAddress((void**)&WoT, g_WoT);
    cudaGetSymbolAddress((void**)&Xr,  g_Xr);

    cudaFuncSetAttribute(flash_h,  cudaFuncAttributeMaxDynamicSharedMemorySize, FLASH_SMEM);
    cudaFuncSetAttribute(qkv_gemm, cudaFuncAttributeMaxDynamicSharedMemorySize, GEMM_SMEM);
    cudaFuncSetAttribute(o_gemm,   cudaFuncAttributeMaxDynamicSharedMemorySize, GEMM_SMEM);

    // prep
    prep_w<<<dim3(64, 64, 4), dim3(32, 8)>>>(Wq, Wk, Wv, Wo);
    f2h_copy<<<MTOT*E_/2/256, 256>>>(x, Xr);
    mask_pack<<<(int)((size_t)B_*S_*S_/256), 256>>>(mask);

    // fused Q/K/V projections (V written transposed)
    qkv_gemm<<<dim3(24, MTOT/128), 256, GEMM_SMEM>>>(bq, bk, bv);

    // attention (3 CTAs/SM)
    flash_h<<<dim3(S_/64, H_, B_), 128, FLASH_SMEM>>>(Od);

    // output projection
    o_gemm<<<dim3(E_/128, MTOT/128), 256, GEMM_SMEM>>>(Od, WoT, bo, out);
}

// round 16
// speedup vs baseline: 1.0338x; 1.0042x over previous
#include <cuda_runtime.h>
#include <cuda_fp16.h>
#include <math.h>
#include <stdint.h>

#define B_  2
#define S_  2048
#define E_  2048
#define H_  16
#define G_  4
#define HD_ 128
#define GD_ 512
#define MTOT (B_*S_)

// ---------------- device scratch (allocation-free rule) ----------------
__device__ __half g_Q [(size_t)B_*H_*S_*HD_];
__device__ __half g_K [(size_t)B_*G_*S_*HD_];
__device__ __half g_Vt[(size_t)B_*G_*HD_*S_];
__device__ __half g_O [(size_t)B_*S_*E_];
__device__ __half g_Xr[(size_t)B_*S_*E_];
__device__ __half g_WqT[(size_t)E_*E_];
__device__ __half g_WkT[(size_t)GD_*E_];
__device__ __half g_WvT[(size_t)GD_*E_];
__device__ __half g_WoT[(size_t)E_*E_];
__device__ unsigned long long g_MB[(size_t)B_*S_*32];

// ---------------- helpers ----------------
__device__ __forceinline__ uint32_t smem_u32(const void* p) {
    uint32_t a;
    asm("{ .reg .u64 t; cvta.to.shared.u64 t, %1; cvt.u32.u64 %0, t; }" : "=r"(a) : "l"(p));
    return a;
}
__device__ __forceinline__ uint32_t pack_h2(float lo, float hi) {
    __half2 v = __floats2half2_rn(lo, hi);
    return *reinterpret_cast<uint32_t*>(&v);
}

#define CP_ASYNC16(dst, src) \
    asm volatile("cp.async.cg.shared.global [%0], [%1], 16;" :: "r"(dst), "l"(src) : "memory")
#define CP_COMMIT() asm volatile("cp.async.commit_group;" ::: "memory")
#define CP_WAIT1()  asm volatile("cp.async.wait_group 1;"  ::: "memory")

__device__ __forceinline__ void mma_f16(float& d0, float& d1, float& d2, float& d3,
                                        uint32_t a0, uint32_t a1, uint32_t a2, uint32_t a3,
                                        uint32_t b0, uint32_t b1) {
    asm volatile("mma.sync.aligned.m16n8k16.row.col.f32.f16.f16.f32 "
                 "{%0,%1,%2,%3},{%4,%5,%6,%7},{%8,%9},{%0,%1,%2,%3};"
                 : "+f"(d0), "+f"(d1), "+f"(d2), "+f"(d3)
                 : "r"(a0), "r"(a1), "r"(a2), "r"(a3), "r"(b0), "r"(b1));
}
__device__ __forceinline__ void ldsm_x4(uint32_t& r0, uint32_t& r1, uint32_t& r2, uint32_t& r3,
                                        uint32_t addr) {
    asm volatile("ldmatrix.sync.aligned.m8n8.x4.shared.b16 {%0,%1,%2,%3}, [%4];"
                 : "=r"(r0), "=r"(r1), "=r"(r2), "=r"(r3) : "r"(addr));
}

// ---------------------------------------------------------------------------
// Prep kernels (unchanged)
// ---------------------------------------------------------------------------
__global__ void prep_w(const float* __restrict__ Wq, const float* __restrict__ Wk,
                       const float* __restrict__ Wv, const float* __restrict__ Wo) {
    __shared__ float tt[32][33];
    const int z = blockIdx.z;
    const int tx = threadIdx.x, ty = threadIdx.y;
    const float* in; __half* out; int Cc;
    if      (z == 0) { in = Wq; out = g_WqT; Cc = E_;  }
    else if (z == 1) { in = Wk; out = g_WkT; Cc = GD_; }
    else if (z == 2) { in = Wv; out = g_WvT; Cc = GD_; }
    else             { in = Wo; out = g_WoT; Cc = E_;  }
    const int c0 = blockIdx.x * 32, r0 = blockIdx.y * 32;
    if (c0 >= Cc) return;
    #pragma unroll
    for (int i = ty; i < 32; i += 8)
        tt[i][tx] = in[(size_t)(r0 + i) * Cc + c0 + tx];
    __syncthreads();
    #pragma unroll
    for (int i = ty; i < 32; i += 8)
        out[(size_t)(c0 + i) * E_ + r0 + tx] = __float2half_rn(tt[tx][i]);
}

__global__ void f2h_copy(const float* __restrict__ in, __half* __restrict__ out) {
    const size_t i = (size_t)blockIdx.x * 256 + threadIdx.x;
    float2 v = *(const float2*)(in + 2*i);
    *(uint32_t*)(out + 2*i) = pack_h2(v.x, v.y);
}

__global__ void mask_pack(const int* __restrict__ mask) {
    const size_t i = (size_t)blockIdx.x * 256 + threadIdx.x;
    const unsigned v = (mask[i] != 0) ? 1u : 0u;
    const unsigned bal = __ballot_sync(0xffffffffu, v);
    if ((threadIdx.x & 31) == 0)
        ((uint32_t*)g_MB)[i >> 5] = bal;
}

// ---------------------------------------------------------------------------
// Fused QKV GEMM (unchanged from R15)
// ---------------------------------------------------------------------------
#define GROW_H 72
#define GROWB  144
#define GSTG_B (128*GROW_H*2)
#define GSTG_PAIR (2*GSTG_B)
#define GEMM_SMEM (3*GSTG_PAIR)      // 110592

__global__ __launch_bounds__(256, 2)
void qkv_gemm(const float* __restrict__ bq, const float* __restrict__ bk,
              const float* __restrict__ bv) {
    extern __shared__ __align__(16) unsigned char gsm[];
    const uint32_t smb = smem_u32(gsm);

    const int t    = threadIdx.x;
    const int lane = t & 31;
    const int wid  = t >> 5;
    const int wm   = wid & 3;
    const int wn   = wid >> 2;
    const int gq   = lane >> 2;
    const int tr   = lane & 3;
    const int lrow = lane & 7, lmat = lane >> 3;
    const int bx = blockIdx.x;
    const int m0 = blockIdx.y * 128;

    const __half* Bw; const float* bias; int nt, heads, vmode;
    if (bx < 16)      { Bw = g_WqT; bias = bq; nt = bx;      heads = 16; vmode = 0; }
    else if (bx < 20) { Bw = g_WkT; bias = bk; nt = bx - 16; heads = 4;  vmode = 0; }
    else              { Bw = g_WvT; bias = bv; nt = bx - 20; heads = 4;  vmode = 1; }
    const int n0 = nt * 128;
    const int K = E_;

    const int row8 = t >> 3, chk = t & 7;
    const __half* Agr = g_Xr + (size_t)(m0 + row8) * K + chk*8;
    const __half* Bgr = Bw   + (size_t)(n0 + row8) * K + chk*8;
    const uint32_t dA = smb + (uint32_t)(row8*GROWB + chk*16);
    const uint32_t dB = dA + GSTG_B;

    const uint32_t aoff = (uint32_t)(((wm*32 + (lmat&1)*8 + lrow)*GROW_H + (lmat>>1)*8) * 2);
    const uint32_t boff = (uint32_t)(((wn*64 + (lmat>>1)*8 + lrow)*GROW_H + (lmat&1)*8) * 2) + GSTG_B;

    float acc[2][8][4];
    #pragma unroll
    for (int i = 0; i < 2; i++)
        #pragma unroll
        for (int j = 0; j < 8; j++)
            #pragma unroll
            for (int r = 0; r < 4; r++) acc[i][j][r] = 0.f;

    const int KT = K >> 6;

    #pragma unroll
    for (int p = 0; p < 2; p++) {
        const int k0 = p * 64;
        #pragma unroll
        for (int i = 0; i < 4; i++) {
            CP_ASYNC16(dA + p*GSTG_PAIR + i*32*GROWB, Agr + (size_t)(i*32)*K + k0);
            CP_ASYNC16(dB + p*GSTG_PAIR + i*32*GROWB, Bgr + (size_t)(i*32)*K + k0);
        }
        CP_COMMIT();
    }

    int s = 0, sl = 2;
    for (int it = 0; it < KT; it++) {
        CP_WAIT1();
        __syncthreads();

        if (it + 2 < KT) {
            const int k0 = (it + 2) * 64;
            const uint32_t so = (uint32_t)(sl * GSTG_PAIR);
            #pragma unroll
            for (int i = 0; i < 4; i++) {
                CP_ASYNC16(dA + so + i*32*GROWB, Agr + (size_t)(i*32)*K + k0);
                CP_ASYNC16(dB + so + i*32*GROWB, Bgr + (size_t)(i*32)*K + k0);
            }
        }
        CP_COMMIT();

        const uint32_t sbase = smb + (uint32_t)(s * GSTG_PAIR);
        #pragma unroll
        for (int ks = 0; ks < 4; ks++) {
            uint32_t a[2][4];
            #pragma unroll
            for (int mf = 0; mf < 2; mf++)
                ldsm_x4(a[mf][0], a[mf][1], a[mf][2], a[mf][3],
                        sbase + aoff + mf*(16*GROWB) + ks*32);
            #pragma unroll
            for (int p = 0; p < 4; p++) {
                uint32_t b0, b1, b2, b3;
                ldsm_x4(b0, b1, b2, b3, sbase + boff + p*(16*GROWB) + ks*32);
                #pragma unroll
                for (int mf = 0; mf < 2; mf++) {
                    mma_f16(acc[mf][2*p][0], acc[mf][2*p][1], acc[mf][2*p][2], acc[mf][2*p][3],
                            a[mf][0], a[mf][1], a[mf][2], a[mf][3], b0, b1);
                    mma_f16(acc[mf][2*p+1][0], acc[mf][2*p+1][1], acc[mf][2*p+1][2], acc[mf][2*p+1][3],
                            a[mf][0], a[mf][1], a[mf][2], a[mf][3], b2, b3);
                }
            }
        }

        s = (s + 1 == 3) ? 0 : s + 1;
        sl = (sl + 1 == 3) ? 0 : sl + 1;
    }

    #pragma unroll
    for (int mf = 0; mf < 2; mf++) {
        const int row0 = m0 + wm*32 + mf*16 + gq;
        const int bb = row0 / S_, ss = row0 % S_;
        #pragma unroll
        for (int nf = 0; nf < 8; nf++) {
            const int col = n0 + wn*64 + nf*8 + tr*2;
            const float b0 = bias[col], b1 = bias[col+1];
            const int dcol = col - n0;
            if (!vmode) {
                __half* C = (bx < 16) ? g_Q : g_K;
                __half* Cp0 = C + (((size_t)(bb*heads + nt))*S_ + ss)*HD_ + dcol;
                *(uint32_t*)Cp0           = pack_h2(acc[mf][nf][0] + b0, acc[mf][nf][1] + b1);
                *(uint32_t*)(Cp0 + 8*HD_) = pack_h2(acc[mf][nf][2] + b0, acc[mf][nf][3] + b1);
            } else {
                __half* base = g_Vt + (((size_t)(bb*G_ + nt))*HD_ + dcol)*S_ + ss;
                base[0]       = __float2half_rn(acc[mf][nf][0] + b0);
                base[S_]      = __float2half_rn(acc[mf][nf][1] + b1);
                base[8]       = __float2half_rn(acc[mf][nf][2] + b0);
                base[S_ + 8]  = __float2half_rn(acc[mf][nf][3] + b1);
            }
        }
    }
}

// ---------------------------------------------------------------------------
// O projection GEMM (unchanged from R15)
// ---------------------------------------------------------------------------
__global__ __launch_bounds__(256, 2)
void o_gemm(const __half* __restrict__ A, const __half* __restrict__ Bw,
            const float* __restrict__ bias, float* __restrict__ C) {
    extern __shared__ __align__(16) unsigned char gsm[];
    const uint32_t smb = smem_u32(gsm);
    const int N = E_, K = E_;

    const int t    = threadIdx.x;
    const int lane = t & 31;
    const int wid  = t >> 5;
    const int wm   = wid & 3;
    const int wn   = wid >> 2;
    const int gq   = lane >> 2;
    const int tr   = lane & 3;
    const int lrow = lane & 7, lmat = lane >> 3;
    const int m0 = blockIdx.y * 128, n0 = blockIdx.x * 128;

    const int row8 = t >> 3, chk = t & 7;
    const __half* Agr = A  + (size_t)(m0 + row8) * K + chk*8;
    const __half* Bgr = Bw + (size_t)(n0 + row8) * K + chk*8;
    const uint32_t dA = smb + (uint32_t)(row8*GROWB + chk*16);
    const uint32_t dB = dA + GSTG_B;

    const uint32_t aoff = (uint32_t)(((wm*32 + (lmat&1)*8 + lrow)*GROW_H + (lmat>>1)*8) * 2);
    const uint32_t boff = (uint32_t)(((wn*64 + (lmat>>1)*8 + lrow)*GROW_H + (lmat&1)*8) * 2) + GSTG_B;

    float acc[2][8][4];
    #pragma unroll
    for (int i = 0; i < 2; i++)
        #pragma unroll
        for (int j = 0; j < 8; j++)
            #pragma unroll
            for (int r = 0; r < 4; r++) acc[i][j][r] = 0.f;

    const int KT = K >> 6;

    #pragma unroll
    for (int p = 0; p < 2; p++) {
        const int k0 = p * 64;
        #pragma unroll
        for (int i = 0; i < 4; i++) {
            CP_ASYNC16(dA + p*GSTG_PAIR + i*32*GROWB, Agr + (size_t)(i*32)*K + k0);
            CP_ASYNC16(dB + p*GSTG_PAIR + i*32*GROWB, Bgr + (size_t)(i*32)*K + k0);
        }
        CP_COMMIT();
    }

    int s = 0, sl = 2;
    for (int it = 0; it < KT; it++) {
        CP_WAIT1();
        __syncthreads();

        if (it + 2 < KT) {
            const int k0 = (it + 2) * 64;
            const uint32_t so = (uint32_t)(sl * GSTG_PAIR);
            #pragma unroll
            for (int i = 0; i < 4; i++) {
                CP_ASYNC16(dA + so + i*32*GROWB, Agr + (size_t)(i*32)*K + k0);
                CP_ASYNC16(dB + so + i*32*GROWB, Bgr + (size_t)(i*32)*K + k0);
            }
        }
        CP_COMMIT();

        const uint32_t sbase = smb + (uint32_t)(s * GSTG_PAIR);
        #pragma unroll
        for (int ks = 0; ks < 4; ks++) {
            uint32_t a[2][4];
            #pragma unroll
            for (int mf = 0; mf < 2; mf++)
                ldsm_x4(a[mf][0], a[mf][1], a[mf][2], a[mf][3],
                        sbase + aoff + mf*(16*GROWB) + ks*32);
            #pragma unroll
            for (int p = 0; p < 4; p++) {
                uint32_t b0, b1, b2, b3;
                ldsm_x4(b0, b1, b2, b3, sbase + boff + p*(16*GROWB) + ks*32);
                #pragma unroll
                for (int mf = 0; mf < 2; mf++) {
                    mma_f16(acc[mf][2*p][0], acc[mf][2*p][1], acc[mf][2*p][2], acc[mf][2*p][3],
                            a[mf][0], a[mf][1], a[mf][2], a[mf][3], b0, b1);
                    mma_f16(acc[mf][2*p+1][0], acc[mf][2*p+1][1], acc[mf][2*p+1][2], acc[mf][2*p+1][3],
                            a[mf][0], a[mf][1], a[mf][2], a[mf][3], b2, b3);
                }
            }
        }

        s = (s + 1 == 3) ? 0 : s + 1;
        sl = (sl + 1 == 3) ? 0 : sl + 1;
    }

    #pragma unroll
    for (int mf = 0; mf < 2; mf++) {
        const int row0 = m0 + wm*32 + mf*16 + gq;
        #pragma unroll
        for (int nf = 0; nf < 8; nf++) {
            const int col = n0 + wn*64 + nf*8 + tr*2;
            const float b0 = bias[col], b1 = bias[col+1];
            float* Cp0 = C + (size_t)row0 * N + col;
            float* Cp1 = Cp0 + (size_t)8 * N;
            *(float2*)Cp0 = make_float2(acc[mf][nf][0] + b0, acc[mf][nf][1] + b1);
            *(float2*)Cp1 = make_float2(acc[mf][nf][2] + b0, acc[mf][nf][3] + b1);
        }
    }
}

// ---------------------------------------------------------------------------
// Flash attention (unchanged from R15: 3 CTAs/SM, base-2 exp2 softmax)
// ---------------------------------------------------------------------------
#define FKROW_H 136
#define FKROWB  272
#define FVROW_H 72
#define FVROWB  144
#define FKSTG_B (64*FKROWB)
#define FVSTG_B (128*FVROWB)
#define FLASH_SMEM (2*FKSTG_B + 2*FVSTG_B)   // 71680

__global__ __launch_bounds__(128, 3)
void flash_h(__half* __restrict__ O) {
    extern __shared__ __align__(16) unsigned char fsm[];
    const int t = threadIdx.x, lane = t & 31, w = t >> 5;
    const int gq = lane >> 2, tr = lane & 3;
    const int lrow = lane & 7, lmat = lane >> 3;
    const int qt = blockIdx.x, h = blockIdx.y, b = blockIdx.z;
    const int g  = h % G_;
    const int q0 = qt * 64;

    const __half* Qg  = g_Q  + (((size_t)(b*H_ + h))*S_ + q0) * HD_;
    const __half* Kg  = g_K  + (((size_t)(b*G_ + g))*S_) * HD_;
    const __half* Vtg = g_Vt + (((size_t)(b*G_ + g))*HD_) * S_;

    const uint32_t uK = smem_u32(fsm);
    const uint32_t uV = uK + 2*FKSTG_B;

    const int krow = t >> 4, kchk = t & 15;
    const int vrow = t >> 3, vchk = t & 7;

    const uint32_t koff = (uint32_t)((((lmat>>1)*8 + lrow)*FKROW_H + (lmat&1)*8) * 2);
    const uint32_t voff = (uint32_t)((((lmat>>1)*8 + lrow)*FVROW_H + (lmat&1)*8) * 2);

    const float scale = 0.12751879523243977f;   // 1/sqrt(128) * log2(e)
    const int qrow = w*16 + gq;
    uint32_t qa[8][4];
    #pragma unroll
    for (int ks = 0; ks < 8; ks++) {
        const int c = ks*16 + tr*2;
        #pragma unroll
        for (int r = 0; r < 4; r++) {
            const int rr = qrow + (r & 1)*8;
            const int cc = c + (r >> 1)*8;
            const uint32_t u = *(const uint32_t*)(Qg + (size_t)rr*HD_ + cc);
            const __half2 hv = *reinterpret_cast<const __half2*>(&u);
            const float2 f = __half22float2(hv);
            qa[ks][r] = pack_h2(f.x*scale, f.y*scale);
        }
    }

    float oc[16][4];
    #pragma unroll
    for (int jf = 0; jf < 16; jf++)
        #pragma unroll
        for (int r = 0; r < 4; r++) oc[jf][r] = 0.f;
    float m0 = -1e30f, m1 = -1e30f, l0 = 0.f, l1 = 0.f;

    #pragma unroll
    for (int i = 0; i < 8; i++)
        CP_ASYNC16(uK + (uint32_t)((krow + 8*i)*FKROWB + kchk*16),
                   Kg + (size_t)(krow + 8*i)*HD_ + kchk*8);
    #pragma unroll
    for (int i = 0; i < 8; i++)
        CP_ASYNC16(uV + (uint32_t)((vrow + 16*i)*FVROWB + vchk*16),
                   Vtg + (size_t)(vrow + 16*i)*S_ + vchk*8);
    CP_COMMIT();

    const unsigned long long* mrow0p = g_MB + ((size_t)(b*S_ + q0 + w*16 + gq)) * 32;
    const unsigned long long* mrow1p = mrow0p + 8*32;

    for (int kt = 0; kt < S_/64; kt++) {
        __syncthreads();
        if (kt + 1 < S_/64) {
            const uint32_t so = ((kt+1) & 1);
            const size_t kvo = (size_t)(kt+1) * 64;
            #pragma unroll
            for (int i = 0; i < 8; i++)
                CP_ASYNC16(uK + so*FKSTG_B + (uint32_t)((krow + 8*i)*FKROWB + kchk*16),
                           Kg + (kvo + krow + 8*i)*HD_ + kchk*8);
            #pragma unroll
            for (int i = 0; i < 8; i++)
                CP_ASYNC16(uV + so*FVSTG_B + (uint32_t)((vrow + 16*i)*FVROWB + vchk*16),
                           Vtg + (size_t)(vrow + 16*i)*S_ + kvo + vchk*8);
        }
        CP_COMMIT();
        CP_WAIT1();
        __syncthreads();

        const uint32_t uKst = uK + (kt & 1)*FKSTG_B;
        const uint32_t uVst = uV + (kt & 1)*FVSTG_B;

        float sc[8][4];
        #pragma unroll
        for (int j = 0; j < 8; j++)
            #pragma unroll
            for (int r = 0; r < 4; r++) sc[j][r] = 0.f;
        #pragma unroll
        for (int ks = 0; ks < 8; ks++) {
            #pragma unroll
            for (int p = 0; p < 4; p++) {
                uint32_t b0, b1, b2, b3;
                ldsm_x4(b0, b1, b2, b3, uKst + koff + p*(16*FKROWB) + ks*32);
                mma_f16(sc[2*p][0], sc[2*p][1], sc[2*p][2], sc[2*p][3],
                        qa[ks][0], qa[ks][1], qa[ks][2], qa[ks][3], b0, b1);
                mma_f16(sc[2*p+1][0], sc[2*p+1][1], sc[2*p+1][2], sc[2*p+1][3],
                        qa[ks][0], qa[ks][1], qa[ks][2], qa[ks][3], b2, b3);
            }
        }

        const unsigned long long mb0 = mrow0p[kt];
        const unsigned long long mb1 = mrow1p[kt];
        float mx0 = -1e30f, mx1 = -1e30f;
        #pragma unroll
        for (int j = 0; j < 8; j++) {
            const int pos = tr*2 + j*8;
            if (!((mb0 >> pos) & 1ULL))       sc[j][0] = -10000.f;
            if (!((mb0 >> (pos+1)) & 1ULL))   sc[j][1] = -10000.f;
            if (!((mb1 >> pos) & 1ULL))       sc[j][2] = -10000.f;
            if (!((mb1 >> (pos+1)) & 1ULL))   sc[j][3] = -10000.f;
            mx0 = fmaxf(mx0, fmaxf(sc[j][0], sc[j][1]));
            mx1 = fmaxf(mx1, fmaxf(sc[j][2], sc[j][3]));
        }
        mx0 = fmaxf(mx0, __shfl_xor_sync(0xffffffffu, mx0, 1));
        mx0 = fmaxf(mx0, __shfl_xor_sync(0xffffffffu, mx0, 2));
        mx1 = fmaxf(mx1, __shfl_xor_sync(0xffffffffu, mx1, 1));
        mx1 = fmaxf(mx1, __shfl_xor_sync(0xffffffffu, mx1, 2));

        const float mn0 = fmaxf(m0, mx0), mn1 = fmaxf(m1, mx1);
        const float f0 = exp2f(m0 - mn0), f1 = exp2f(m1 - mn1);
        m0 = mn0; m1 = mn1;

        float s0 = 0.f, s1 = 0.f;
        #pragma unroll
        for (int j = 0; j < 8; j++) {
            sc[j][0] = exp2f(sc[j][0] - mn0); s0 += sc[j][0];
            sc[j][1] = exp2f(sc[j][1] - mn0); s0 += sc[j][1];
            sc[j][2] = exp2f(sc[j][2] - mn1); s1 += sc[j][2];
            sc[j][3] = exp2f(sc[j][3] - mn1); s1 += sc[j][3];
        }
        s0 += __shfl_xor_sync(0xffffffffu, s0, 1);
        s0 += __shfl_xor_sync(0xffffffffu, s0, 2);
        s1 += __shfl_xor_sync(0xffffffffu, s1, 1);
        s1 += __shfl_xor_sync(0xffffffffu, s1, 2);
        l0 = l0 * f0 + s0;
        l1 = l1 * f1 + s1;

        #pragma unroll
        for (int jf = 0; jf < 16; jf++) {
            oc[jf][0] *= f0; oc[jf][1] *= f0;
            oc[jf][2] *= f1; oc[jf][3] *= f1;
        }

        #pragma unroll
        for (int ks = 0; ks < 4; ks++) {
            const uint32_t a0 = pack_h2(sc[2*ks][0],   sc[2*ks][1]);
            const uint32_t a1 = pack_h2(sc[2*ks][2],   sc[2*ks][3]);
            const uint32_t a2 = pack_h2(sc[2*ks+1][0], sc[2*ks+1][1]);
            const uint32_t a3 = pack_h2(sc[2*ks+1][2], sc[2*ks+1][3]);
            #pragma unroll
            for (int p = 0; p < 8; p++) {
                uint32_t b0, b1, b2, b3;
                ldsm_x4(b0, b1, b2, b3, uVst + voff + p*(16*FVROWB) + ks*32);
                mma_f16(oc[2*p][0], oc[2*p][1], oc[2*p][2], oc[2*p][3],
                        a0, a1, a2, a3, b0, b1);
                mma_f16(oc[2*p+1][0], oc[2*p+1][1], oc[2*p+1][2], oc[2*p+1][3],
                        a0, a1, a2, a3, b2, b3);
            }
        }
    }

    const float inv0 = 1.f / l0, inv1 = 1.f / l1;
    __half* O0 = O + ((size_t)(b*S_ + q0 + w*16 + gq)) * E_ + h*HD_;
    __half* O1 = O0 + (size_t)8 * E_;
    #pragma unroll
    for (int jf = 0; jf < 16; jf++) {
        const int c = jf*8 + tr*2;
        *(uint32_t*)(O0 + c) = pack_h2(oc[jf][0]*inv0, oc[jf][1]*inv0);
        *(uint32_t*)(O1 + c) = pack_h2(oc[jf][2]*inv1, oc[jf][3]*inv1);
    }
}

// ---------------------------------------------------------------------------
extern "C" void kernel_launch(void* const* d_in, const int* in_sizes, int n_in,
                              void* d_out, int out_size) {
    const float* x  = (const float*)d_in[0];
    const int* mask = (const int*)  d_in[1];
    const float* Wq = (const float*)d_in[2];
    const float* bq = (const float*)d_in[3];
    const float* Wk = (const float*)d_in[4];
    const float* bk = (const float*)d_in[5];
    const float* Wv = (const float*)d_in[6];
    const float* bv = (const float*)d_in[7];
    const float* Wo = (const float*)d_in[8];
    const float* bo = (const float*)d_in[9];
    float* out = (float*)d_out;

    __half *Od, *WoT, *Xr;
    cudaGetSymbolAddress((void**)&Od,  g_O);
    cudaGetSymbolAddress((void**)&WoT, g_WoT);
    cudaGetSymbolAddress((void**)&Xr,  g_Xr);

    cudaFuncSetAttribute(flash_h,  cudaFuncAttributeMaxDynamicSharedMemorySize, FLASH_SMEM);
    cudaFuncSetAttribute(qkv_gemm, cudaFuncAttributeMaxDynamicSharedMemorySize, GEMM_SMEM);
    cudaFuncSetAttribute(o_gemm,   cudaFuncAttributeMaxDynamicSharedMemorySize, GEMM_SMEM);

    // side stream + events (created once on the first, non-captured, call)
    static cudaStream_t s2 = nullptr;
    static cudaEvent_t eFork = nullptr, eXr = nullptr, eMask = nullptr;
    if (!s2) {
        cudaStreamCreateWithFlags(&s2, cudaStreamNonBlocking);
        cudaEventCreateWithFlags(&eFork, cudaEventDisableTiming);
        cudaEventCreateWithFlags(&eXr,   cudaEventDisableTiming);
        cudaEventCreateWithFlags(&eMask, cudaEventDisableTiming);
    }

    // fork side stream from main (legacy) stream
    cudaEventRecord(eFork, 0);
    cudaStreamWaitEvent(s2, eFork, 0);

    // side stream: x->fp16 (needed by qkv), then mask bits (needed by flash)
    f2h_copy<<<MTOT*E_/2/256, 256, 0, s2>>>(x, Xr);
    cudaEventRecord(eXr, s2);
    mask_pack<<<(int)((size_t)B_*S_*S_/256), 256, 0, s2>>>(mask);
    cudaEventRecord(eMask, s2);

    // main stream: weight transposes (concurrent with f2h)
    prep_w<<<dim3(64, 64, 4), dim3(32, 8)>>>(Wq, Wk, Wv, Wo);

    // qkv needs weights (main-order) + Xr (event)
    cudaStreamWaitEvent(0, eXr, 0);
    qkv_gemm<<<dim3(24, MTOT/128), 256, GEMM_SMEM>>>(bq, bk, bv);

    // flash additionally needs the packed mask (runs concurrent with qkv)
    cudaStreamWaitEvent(0, eMask, 0);
    flash_h<<<dim3(S_/64, H_, B_), 128, FLASH_SMEM>>>(Od);

    // output projection
    o_gemm<<<dim3(E_/128, MTOT/128), 256, GEMM_SMEM>>>(Od, WoT, bo, out);
}

// round 17
// speedup vs baseline: 1.0561x; 1.0216x over previous
#include <cuda_runtime.h>
#include <cuda_fp16.h>
#include <math.h>
#include <stdint.h>

#define B_  2
#define S_  2048
#define E_  2048
#define H_  16
#define G_  4
#define HD_ 128
#define GD_ 512
#define MTOT (B_*S_)

// ---------------- device scratch (allocation-free rule) ----------------
__device__ __half g_Q [(size_t)B_*H_*S_*HD_];
__device__ __half g_K [(size_t)B_*G_*S_*HD_];
__device__ __half g_Vt[(size_t)B_*G_*HD_*S_];
__device__ __half g_O [(size_t)B_*S_*E_];
__device__ __half g_Xr[(size_t)B_*S_*E_];
__device__ __half g_WqT[(size_t)E_*E_];
__device__ __half g_WkT[(size_t)GD_*E_];
__device__ __half g_WvT[(size_t)GD_*E_];
__device__ __half g_WoT[(size_t)E_*E_];
__device__ unsigned long long g_MB[(size_t)B_*S_*32];

// ---------------- helpers ----------------
__device__ __forceinline__ uint32_t smem_u32(const void* p) {
    uint32_t a;
    asm("{ .reg .u64 t; cvta.to.shared.u64 t, %1; cvt.u32.u64 %0, t; }" : "=r"(a) : "l"(p));
    return a;
}
__device__ __forceinline__ uint32_t pack_h2(float lo, float hi) {
    __half2 v = __floats2half2_rn(lo, hi);
    return *reinterpret_cast<uint32_t*>(&v);
}

#define CP_ASYNC16(dst, src) \
    asm volatile("cp.async.cg.shared.global [%0], [%1], 16;" :: "r"(dst), "l"(src) : "memory")
#define CP_COMMIT() asm volatile("cp.async.commit_group;" ::: "memory")
#define CP_WAIT1()  asm volatile("cp.async.wait_group 1;"  ::: "memory")

__device__ __forceinline__ void mma_f16(float& d0, float& d1, float& d2, float& d3,
                                        uint32_t a0, uint32_t a1, uint32_t a2, uint32_t a3,
                                        uint32_t b0, uint32_t b1) {
    asm volatile("mma.sync.aligned.m16n8k16.row.col.f32.f16.f16.f32 "
                 "{%0,%1,%2,%3},{%4,%5,%6,%7},{%8,%9},{%0,%1,%2,%3};"
                 : "+f"(d0), "+f"(d1), "+f"(d2), "+f"(d3)
                 : "r"(a0), "r"(a1), "r"(a2), "r"(a3), "r"(b0), "r"(b1));
}
__device__ __forceinline__ void ldsm_x4(uint32_t& r0, uint32_t& r1, uint32_t& r2, uint32_t& r3,
                                        uint32_t addr) {
    asm volatile("ldmatrix.sync.aligned.m8n8.x4.shared.b16 {%0,%1,%2,%3}, [%4];"
                 : "=r"(r0), "=r"(r1), "=r"(r2), "=r"(r3) : "r"(addr));
}

// ---------------------------------------------------------------------------
// Prep kernels
// ---------------------------------------------------------------------------
// Compact 1-D grid: tiles laid out as [Wq: 64x64][Wk: 16x64][Wv: 16x64][Wo: 64x64]
#define WQ_TILES (64*64)
#define WK_TILES (16*64)
#define PREPW_BLOCKS (2*WQ_TILES + 2*WK_TILES)   // 10240

__global__ void prep_w(const float* __restrict__ Wq, const float* __restrict__ Wk,
                       const float* __restrict__ Wv, const float* __restrict__ Wo) {
    __shared__ float tt[32][33];
    const int tx = threadIdx.x, ty = threadIdx.y;
    int id = blockIdx.x;
    const float* in; __half* out; int Cc, tilesx;
    if (id < WQ_TILES)                    { in = Wq; out = g_WqT; Cc = E_;  tilesx = 64; }
    else if ((id -= WQ_TILES) < WK_TILES) { in = Wk; out = g_WkT; Cc = GD_; tilesx = 16; }
    else if ((id -= WK_TILES) < WK_TILES) { in = Wv; out = g_WvT; Cc = GD_; tilesx = 16; }
    else { id -= WK_TILES;                  in = Wo; out = g_WoT; Cc = E_;  tilesx = 64; }
    const int c0 = (id % tilesx) * 32, r0 = (id / tilesx) * 32;
    #pragma unroll
    for (int i = ty; i < 32; i += 8)
        tt[i][tx] = in[(size_t)(r0 + i) * Cc + c0 + tx];
    __syncthreads();
    #pragma unroll
    for (int i = ty; i < 32; i += 8)
        out[(size_t)(c0 + i) * E_ + r0 + tx] = __float2half_rn(tt[tx][i]);
}

__global__ void f2h_copy(const float* __restrict__ in, __half* __restrict__ out) {
    const size_t i = (size_t)blockIdx.x * 256 + threadIdx.x;
    float2 v = *(const float2*)(in + 2*i);
    *(uint32_t*)(out + 2*i) = pack_h2(v.x, v.y);
}

// int4-vectorized: each thread packs 4 mask ints -> 4 bits of the ballot nibble
__global__ void mask_pack(const int* __restrict__ mask) {
    const size_t i4 = (size_t)blockIdx.x * 256 + threadIdx.x;   // int4 index
    const int4 v = ((const int4*)mask)[i4];
    unsigned nib = (v.x != 0 ? 1u : 0u) | (v.y != 0 ? 2u : 0u)
                 | (v.z != 0 ? 4u : 0u) | (v.w != 0 ? 8u : 0u);
    // 8 consecutive lanes cover one uint32 of bits
    unsigned word = nib << (4 * (threadIdx.x & 7));
    #pragma unroll
    for (int o = 1; o < 8; o <<= 1)
        word |= __shfl_xor_sync(0xffffffffu, word, o);
    if ((threadIdx.x & 7) == 0)
        ((uint32_t*)g_MB)[i4 >> 3] = word;
}

// ---------------------------------------------------------------------------
// Fused QKV GEMM (unchanged)
// ---------------------------------------------------------------------------
#define GROW_H 72
#define GROWB  144
#define GSTG_B (128*GROW_H*2)
#define GSTG_PAIR (2*GSTG_B)
#define GEMM_SMEM (3*GSTG_PAIR)      // 110592

__global__ __launch_bounds__(256, 2)
void qkv_gemm(const float* __restrict__ bq, const float* __restrict__ bk,
              const float* __restrict__ bv) {
    extern __shared__ __align__(16) unsigned char gsm[];
    const uint32_t smb = smem_u32(gsm);

    const int t    = threadIdx.x;
    const int lane = t & 31;
    const int wid  = t >> 5;
    const int wm   = wid & 3;
    const int wn   = wid >> 2;
    const int gq   = lane >> 2;
    const int tr   = lane & 3;
    const int lrow = lane & 7, lmat = lane >> 3;
    const int bx = blockIdx.x;
    const int m0 = blockIdx.y * 128;

    const __half* Bw; const float* bias; int nt, heads, vmode;
    if (bx < 16)      { Bw = g_WqT; bias = bq; nt = bx;      heads = 16; vmode = 0; }
    else if (bx < 20) { Bw = g_WkT; bias = bk; nt = bx - 16; heads = 4;  vmode = 0; }
    else              { Bw = g_WvT; bias = bv; nt = bx - 20; heads = 4;  vmode = 1; }
    const int n0 = nt * 128;
    const int K = E_;

    const int row8 = t >> 3, chk = t & 7;
    const __half* Agr = g_Xr + (size_t)(m0 + row8) * K + chk*8;
    const __half* Bgr = Bw   + (size_t)(n0 + row8) * K + chk*8;
    const uint32_t dA = smb + (uint32_t)(row8*GROWB + chk*16);
    const uint32_t dB = dA + GSTG_B;

    const uint32_t aoff = (uint32_t)(((wm*32 + (lmat&1)*8 + lrow)*GROW_H + (lmat>>1)*8) * 2);
    const uint32_t boff = (uint32_t)(((wn*64 + (lmat>>1)*8 + lrow)*GROW_H + (lmat&1)*8) * 2) + GSTG_B;

    float acc[2][8][4];
    #pragma unroll
    for (int i = 0; i < 2; i++)
        #pragma unroll
        for (int j = 0; j < 8; j++)
            #pragma unroll
            for (int r = 0; r < 4; r++) acc[i][j][r] = 0.f;

    const int KT = K >> 6;

    #pragma unroll
    for (int p = 0; p < 2; p++) {
        const int k0 = p * 64;
        #pragma unroll
        for (int i = 0; i < 4; i++) {
            CP_ASYNC16(dA + p*GSTG_PAIR + i*32*GROWB, Agr + (size_t)(i*32)*K + k0);
            CP_ASYNC16(dB + p*GSTG_PAIR + i*32*GROWB, Bgr + (size_t)(i*32)*K + k0);
        }
        CP_COMMIT();
    }

    int s = 0, sl = 2;
    for (int it = 0; it < KT; it++) {
        CP_WAIT1();
        __syncthreads();

        if (it + 2 < KT) {
            const int k0 = (it + 2) * 64;
            const uint32_t so = (uint32_t)(sl * GSTG_PAIR);
            #pragma unroll
            for (int i = 0; i < 4; i++) {
                CP_ASYNC16(dA + so + i*32*GROWB, Agr + (size_t)(i*32)*K + k0);
                CP_ASYNC16(dB + so + i*32*GROWB, Bgr + (size_t)(i*32)*K + k0);
            }
        }
        CP_COMMIT();

        const uint32_t sbase = smb + (uint32_t)(s * GSTG_PAIR);
        #pragma unroll
        for (int ks = 0; ks < 4; ks++) {
            uint32_t a[2][4];
            #pragma unroll
            for (int mf = 0; mf < 2; mf++)
                ldsm_x4(a[mf][0], a[mf][1], a[mf][2], a[mf][3],
                        sbase + aoff + mf*(16*GROWB) + ks*32);
            #pragma unroll
            for (int p = 0; p < 4; p++) {
                uint32_t b0, b1, b2, b3;
                ldsm_x4(b0, b1, b2, b3, sbase + boff + p*(16*GROWB) + ks*32);
                #pragma unroll
                for (int mf = 0; mf < 2; mf++) {
                    mma_f16(acc[mf][2*p][0], acc[mf][2*p][1], acc[mf][2*p][2], acc[mf][2*p][3],
                            a[mf][0], a[mf][1], a[mf][2], a[mf][3], b0, b1);
                    mma_f16(acc[mf][2*p+1][0], acc[mf][2*p+1][1], acc[mf][2*p+1][2], acc[mf][2*p+1][3],
                            a[mf][0], a[mf][1], a[mf][2], a[mf][3], b2, b3);
                }
            }
        }

        s = (s + 1 == 3) ? 0 : s + 1;
        sl = (sl + 1 == 3) ? 0 : sl + 1;
    }

    #pragma unroll
    for (int mf = 0; mf < 2; mf++) {
        const int row0 = m0 + wm*32 + mf*16 + gq;
        const int bb = row0 / S_, ss = row0 % S_;
        #pragma unroll
        for (int nf = 0; nf < 8; nf++) {
            const int col = n0 + wn*64 + nf*8 + tr*2;
            const float b0 = bias[col], b1 = bias[col+1];
            const int dcol = col - n0;
            if (!vmode) {
                __half* C = (bx < 16) ? g_Q : g_K;
                __half* Cp0 = C + (((size_t)(bb*heads + nt))*S_ + ss)*HD_ + dcol;
                *(uint32_t*)Cp0           = pack_h2(acc[mf][nf][0] + b0, acc[mf][nf][1] + b1);
                *(uint32_t*)(Cp0 + 8*HD_) = pack_h2(acc[mf][nf][2] + b0, acc[mf][nf][3] + b1);
            } else {
                __half* base = g_Vt + (((size_t)(bb*G_ + nt))*HD_ + dcol)*S_ + ss;
                base[0]       = __float2half_rn(acc[mf][nf][0] + b0);
                base[S_]      = __float2half_rn(acc[mf][nf][1] + b1);
                base[8]       = __float2half_rn(acc[mf][nf][2] + b0);
                base[S_ + 8]  = __float2half_rn(acc[mf][nf][3] + b1);
            }
        }
    }
}

// ---------------------------------------------------------------------------
// O projection GEMM (unchanged)
// ---------------------------------------------------------------------------
__global__ __launch_bounds__(256, 2)
void o_gemm(const __half* __restrict__ A, const __half* __restrict__ Bw,
            const float* __restrict__ bias, float* __restrict__ C) {
    extern __shared__ __align__(16) unsigned char gsm[];
    const uint32_t smb = smem_u32(gsm);
    const int N = E_, K = E_;

    const int t    = threadIdx.x;
    const int lane = t & 31;
    const int wid  = t >> 5;
    const int wm   = wid & 3;
    const int wn   = wid >> 2;
    const int gq   = lane >> 2;
    const int tr   = lane & 3;
    const int lrow = lane & 7, lmat = lane >> 3;
    const int m0 = blockIdx.y * 128, n0 = blockIdx.x * 128;

    const int row8 = t >> 3, chk = t & 7;
    const __half* Agr = A  + (size_t)(m0 + row8) * K + chk*8;
    const __half* Bgr = Bw + (size_t)(n0 + row8) * K + chk*8;
    const uint32_t dA = smb + (uint32_t)(row8*GROWB + chk*16);
    const uint32_t dB = dA + GSTG_B;

    const uint32_t aoff = (uint32_t)(((wm*32 + (lmat&1)*8 + lrow)*GROW_H + (lmat>>1)*8) * 2);
    const uint32_t boff = (uint32_t)(((wn*64 + (lmat>>1)*8 + lrow)*GROW_H + (lmat&1)*8) * 2) + GSTG_B;

    float acc[2][8][4];
    #pragma unroll
    for (int i = 0; i < 2; i++)
        #pragma unroll
        for (int j = 0; j < 8; j++)
            #pragma unroll
            for (int r = 0; r < 4; r++) acc[i][j][r] = 0.f;

    const int KT = K >> 6;

    #pragma unroll
    for (int p = 0; p < 2; p++) {
        const int k0 = p * 64;
        #pragma unroll
        for (int i = 0; i < 4; i++) {
            CP_ASYNC16(dA + p*GSTG_PAIR + i*32*GROWB, Agr + (size_t)(i*32)*K + k0);
            CP_ASYNC16(dB + p*GSTG_PAIR + i*32*GROWB, Bgr + (size_t)(i*32)*K + k0);
        }
        CP_COMMIT();
    }

    int s = 0, sl = 2;
    for (int it = 0; it < KT; it++) {
        CP_WAIT1();
        __syncthreads();

        if (it + 2 < KT) {
            const int k0 = (it + 2) * 64;
            const uint32_t so = (uint32_t)(sl * GSTG_PAIR);
            #pragma unroll
            for (int i = 0; i < 4; i++) {
                CP_ASYNC16(dA + so + i*32*GROWB, Agr + (size_t)(i*32)*K + k0);
                CP_ASYNC16(dB + so + i*32*GROWB, Bgr + (size_t)(i*32)*K + k0);
            }
        }
        CP_COMMIT();

        const uint32_t sbase = smb + (uint32_t)(s * GSTG_PAIR);
        #pragma unroll
        for (int ks = 0; ks < 4; ks++) {
            uint32_t a[2][4];
            #pragma unroll
            for (int mf = 0; mf < 2; mf++)
                ldsm_x4(a[mf][0], a[mf][1], a[mf][2], a[mf][3],
                        sbase + aoff + mf*(16*GROWB) + ks*32);
            #pragma unroll
            for (int p = 0; p < 4; p++) {
                uint32_t b0, b1, b2, b3;
                ldsm_x4(b0, b1, b2, b3, sbase + boff + p*(16*GROWB) + ks*32);
                #pragma unroll
                for (int mf = 0; mf < 2; mf++) {
                    mma_f16(acc[mf][2*p][0], acc[mf][2*p][1], acc[mf][2*p][2], acc[mf][2*p][3],
                            a[mf][0], a[mf][1], a[mf][2], a[mf][3], b0, b1);
                    mma_f16(acc[mf][2*p+1][0], acc[mf][2*p+1][1], acc[mf][2*p+1][2], acc[mf][2*p+1][3],
                            a[mf][0], a[mf][1], a[mf][2], a[mf][3], b2, b3);
                }
            }
        }

        s = (s + 1 == 3) ? 0 : s + 1;
        sl = (sl + 1 == 3) ? 0 : sl + 1;
    }

    #pragma unroll
    for (int mf = 0; mf < 2; mf++) {
        const int row0 = m0 + wm*32 + mf*16 + gq;
        #pragma unroll
        for (int nf = 0; nf < 8; nf++) {
            const int col = n0 + wn*64 + nf*8 + tr*2;
            const float b0 = bias[col], b1 = bias[col+1];
            float* Cp0 = C + (size_t)row0 * N + col;
            float* Cp1 = Cp0 + (size_t)8 * N;
            *(float2*)Cp0 = make_float2(acc[mf][nf][0] + b0, acc[mf][nf][1] + b1);
            *(float2*)Cp1 = make_float2(acc[mf][nf][2] + b0, acc[mf][nf][3] + b1);
        }
    }
}

// ---------------------------------------------------------------------------
// Flash attention (unchanged: 3 CTAs/SM, base-2 exp2 softmax)
// ---------------------------------------------------------------------------
#define FKROW_H 136
#define FKROWB  272
#define FVROW_H 72
#define FVROWB  144
#define FKSTG_B (64*FKROWB)
#define FVSTG_B (128*FVROWB)
#define FLASH_SMEM (2*FKSTG_B + 2*FVSTG_B)   // 71680

__global__ __launch_bounds__(128, 3)
void flash_h(__half* __restrict__ O) {
    extern __shared__ __align__(16) unsigned char fsm[];
    const int t = threadIdx.x, lane = t & 31, w = t >> 5;
    const int gq = lane >> 2, tr = lane & 3;
    const int lrow = lane & 7, lmat = lane >> 3;
    const int qt = blockIdx.x, h = blockIdx.y, b = blockIdx.z;
    const int g  = h % G_;
    const int q0 = qt * 64;

    const __half* Qg  = g_Q  + (((size_t)(b*H_ + h))*S_ + q0) * HD_;
    const __half* Kg  = g_K  + (((size_t)(b*G_ + g))*S_) * HD_;
    const __half* Vtg = g_Vt + (((size_t)(b*G_ + g))*HD_) * S_;

    const uint32_t uK = smem_u32(fsm);
    const uint32_t uV = uK + 2*FKSTG_B;

    const int krow = t >> 4, kchk = t & 15;
    const int vrow = t >> 3, vchk = t & 7;

    const uint32_t koff = (uint32_t)((((lmat>>1)*8 + lrow)*FKROW_H + (lmat&1)*8) * 2);
    const uint32_t voff = (uint32_t)((((lmat>>1)*8 + lrow)*FVROW_H + (lmat&1)*8) * 2);

    const float scale = 0.12751879523243977f;   // 1/sqrt(128) * log2(e)
    const int qrow = w*16 + gq;
    uint32_t qa[8][4];
    #pragma unroll
    for (int ks = 0; ks < 8; ks++) {
        const int c = ks*16 + tr*2;
        #pragma unroll
        for (int r = 0; r < 4; r++) {
            const int rr = qrow + (r & 1)*8;
            const int cc = c + (r >> 1)*8;
            const uint32_t u = *(const uint32_t*)(Qg + (size_t)rr*HD_ + cc);
            const __half2 hv = *reinterpret_cast<const __half2*>(&u);
            const float2 f = __half22float2(hv);
            qa[ks][r] = pack_h2(f.x*scale, f.y*scale);
        }
    }

    float oc[16][4];
    #pragma unroll
    for (int jf = 0; jf < 16; jf++)
        #pragma unroll
        for (int r = 0; r < 4; r++) oc[jf][r] = 0.f;
    float m0 = -1e30f, m1 = -1e30f, l0 = 0.f, l1 = 0.f;

    #pragma unroll
    for (int i = 0; i < 8; i++)
        CP_ASYNC16(uK + (uint32_t)((krow + 8*i)*FKROWB + kchk*16),
                   Kg + (size_t)(krow + 8*i)*HD_ + kchk*8);
    #pragma unroll
    for (int i = 0; i < 8; i++)
        CP_ASYNC16(uV + (uint32_t)((vrow + 16*i)*FVROWB + vchk*16),
                   Vtg + (size_t)(vrow + 16*i)*S_ + vchk*8);
    CP_COMMIT();

    const unsigned long long* mrow0p = g_MB + ((size_t)(b*S_ + q0 + w*16 + gq)) * 32;
    const unsigned long long* mrow1p = mrow0p + 8*32;

    for (int kt = 0; kt < S_/64; kt++) {
        __syncthreads();
        if (kt + 1 < S_/64) {
            const uint32_t so = ((kt+1) & 1);
            const size_t kvo = (size_t)(kt+1) * 64;
            #pragma unroll
            for (int i = 0; i < 8; i++)
                CP_ASYNC16(uK + so*FKSTG_B + (uint32_t)((krow + 8*i)*FKROWB + kchk*16),
                           Kg + (kvo + krow + 8*i)*HD_ + kchk*8);
            #pragma unroll
            for (int i = 0; i < 8; i++)
                CP_ASYNC16(uV + so*FVSTG_B + (uint32_t)((vrow + 16*i)*FVROWB + vchk*16),
                           Vtg + (size_t)(vrow + 16*i)*S_ + kvo + vchk*8);
        }
        CP_COMMIT();
        CP_WAIT1();
        __syncthreads();

        const uint32_t uKst = uK + (kt & 1)*FKSTG_B;
        const uint32_t uVst = uV + (kt & 1)*FVSTG_B;

        float sc[8][4];
        #pragma unroll
        for (int j = 0; j < 8; j++)
            #pragma unroll
            for (int r = 0; r < 4; r++) sc[j][r] = 0.f;
        #pragma unroll
        for (int ks = 0; ks < 8; ks++) {
            #pragma unroll
            for (int p = 0; p < 4; p++) {
                uint32_t b0, b1, b2, b3;
                ldsm_x4(b0, b1, b2, b3, uKst + koff + p*(16*FKROWB) + ks*32);
                mma_f16(sc[2*p][0], sc[2*p][1], sc[2*p][2], sc[2*p][3],
                        qa[ks][0], qa[ks][1], qa[ks][2], qa[ks][3], b0, b1);
                mma_f16(sc[2*p+1][0], sc[2*p+1][1], sc[2*p+1][2], sc[2*p+1][3],
                        qa[ks][0], qa[ks][1], qa[ks][2], qa[ks][3], b2, b3);
            }
        }

        const unsigned long long mb0 = mrow0p[kt];
        const unsigned long long mb1 = mrow1p[kt];
        float mx0 = -1e30f, mx1 = -1e30f;
        #pragma unroll
        for (int j = 0; j < 8; j++) {
            const int pos = tr*2 + j*8;
            if (!((mb0 >> pos) & 1ULL))       sc[j][0] = -10000.f;
            if (!((mb0 >> (pos+1)) & 1ULL))   sc[j][1] = -10000.f;
            if (!((mb1 >> pos) & 1ULL))       sc[j][2] = -10000.f;
            if (!((mb1 >> (pos+1)) & 1ULL))   sc[j][3] = -10000.f;
            mx0 = fmaxf(mx0, fmaxf(sc[j][0], sc[j][1]));
            mx1 = fmaxf(mx1, fmaxf(sc[j][2], sc[j][3]));
        }
        mx0 = fmaxf(mx0, __shfl_xor_sync(0xffffffffu, mx0, 1));
        mx0 = fmaxf(mx0, __shfl_xor_sync(0xffffffffu, mx0, 2));
        mx1 = fmaxf(mx1, __shfl_xor_sync(0xffffffffu, mx1, 1));
        mx1 = fmaxf(mx1, __shfl_xor_sync(0xffffffffu, mx1, 2));

        const float mn0 = fmaxf(m0, mx0), mn1 = fmaxf(m1, mx1);
        const float f0 = exp2f(m0 - mn0), f1 = exp2f(m1 - mn1);
        m0 = mn0; m1 = mn1;

        float s0 = 0.f, s1 = 0.f;
        #pragma unroll
        for (int j = 0; j < 8; j++) {
            sc[j][0] = exp2f(sc[j][0] - mn0); s0 += sc[j][0];
            sc[j][1] = exp2f(sc[j][1] - mn0); s0 += sc[j][1];
            sc[j][2] = exp2f(sc[j][2] - mn1); s1 += sc[j][2];
            sc[j][3] = exp2f(sc[j][3] - mn1); s1 += sc[j][3];
        }
        s0 += __shfl_xor_sync(0xffffffffu, s0, 1);
        s0 += __shfl_xor_sync(0xffffffffu, s0, 2);
        s1 += __shfl_xor_sync(0xffffffffu, s1, 1);
        s1 += __shfl_xor_sync(0xffffffffu, s1, 2);
        l0 = l0 * f0 + s0;
        l1 = l1 * f1 + s1;

        #pragma unroll
        for (int jf = 0; jf < 16; jf++) {
            oc[jf][0] *= f0; oc[jf][1] *= f0;
            oc[jf][2] *= f1; oc[jf][3] *= f1;
        }

        #pragma unroll
        for (int ks = 0; ks < 4; ks++) {
            const uint32_t a0 = pack_h2(sc[2*ks][0],   sc[2*ks][1]);
            const uint32_t a1 = pack_h2(sc[2*ks][2],   sc[2*ks][3]);
            const uint32_t a2 = pack_h2(sc[2*ks+1][0], sc[2*ks+1][1]);
            const uint32_t a3 = pack_h2(sc[2*ks+1][2], sc[2*ks+1][3]);
            #pragma unroll
            for (int p = 0; p < 8; p++) {
                uint32_t b0, b1, b2, b3;
                ldsm_x4(b0, b1, b2, b3, uVst + voff + p*(16*FVROWB) + ks*32);
                mma_f16(oc[2*p][0], oc[2*p][1], oc[2*p][2], oc[2*p][3],
                        a0, a1, a2, a3, b0, b1);
                mma_f16(oc[2*p+1][0], oc[2*p+1][1], oc[2*p+1][2], oc[2*p+1][3],
                        a0, a1, a2, a3, b2, b3);
            }
        }
    }

    const float inv0 = 1.f / l0, inv1 = 1.f / l1;
    __half* O0 = O + ((size_t)(b*S_ + q0 + w*16 + gq)) * E_ + h*HD_;
    __half* O1 = O0 + (size_t)8 * E_;
    #pragma unroll
    for (int jf = 0; jf < 16; jf++) {
        const int c = jf*8 + tr*2;
        *(uint32_t*)(O0 + c) = pack_h2(oc[jf][0]*inv0, oc[jf][1]*inv0);
        *(uint32_t*)(O1 + c) = pack_h2(oc[jf][2]*inv1, oc[jf][3]*inv1);
    }
}

// ---------------------------------------------------------------------------
extern "C" void kernel_launch(void* const* d_in, const int* in_sizes, int n_in,
                              void* d_out, int out_size) {
    const float* x  = (const float*)d_in[0];
    const int* mask = (const int*)  d_in[1];
    const float* Wq = (const float*)d_in[2];
    const float* bq = (const float*)d_in[3];
    const float* Wk = (const float*)d_in[4];
    const float* bk = (const float*)d_in[5];
    const float* Wv = (const float*)d_in[6];
    const float* bv = (const float*)d_in[7];
    const float* Wo = (const float*)d_in[8];
    const float* bo = (const float*)d_in[9];
    float* out = (float*)d_out;

    __half *Od, *WoT, *Xr;
    cudaGetSymbolAddress((void**)&Od,  g_O);
    cudaGetSymbolAddress((void**)&WoT, g_WoT);
    cudaGetSymbolAddress((void**)&Xr,  g_Xr);

    cudaFuncSetAttribute(flash_h,  cudaFuncAttributeMaxDynamicSharedMemorySize, FLASH_SMEM);
    cudaFuncSetAttribute(qkv_gemm, cudaFuncAttributeMaxDynamicSharedMemorySize, GEMM_SMEM);
    cudaFuncSetAttribute(o_gemm,   cudaFuncAttributeMaxDynamicSharedMemorySize, GEMM_SMEM);

    // side stream + events (created once on the first, non-captured, call)
    static cudaStream_t s2 = nullptr;
    static cudaEvent_t eFork = nullptr, eXr = nullptr, eMask = nullptr;
    if (!s2) {
        cudaStreamCreateWithFlags(&s2, cudaStreamNonBlocking);
        cudaEventCreateWithFlags(&eFork, cudaEventDisableTiming);
        cudaEventCreateWithFlags(&eXr,   cudaEventDisableTiming);
        cudaEventCreateWithFlags(&eMask, cudaEventDisableTiming);
    }

    // fork side stream from main (legacy) stream
    cudaEventRecord(eFork, 0);
    cudaStreamWaitEvent(s2, eFork, 0);

    // side stream: x->fp16 (needed by qkv), then mask bits (needed by flash)
    f2h_copy<<<MTOT*E_/2/256, 256, 0, s2>>>(x, Xr);
    cudaEventRecord(eXr, s2);
    mask_pack<<<(int)((size_t)B_*S_*S_/4/256), 256, 0, s2>>>(mask);
    cudaEventRecord(eMask, s2);

    // main stream: weight transposes (concurrent with f2h)
    prep_w<<<PREPW_BLOCKS, dim3(32, 8)>>>(Wq, Wk, Wv, Wo);

    // qkv needs weights (main-order) + Xr (event)
    cudaStreamWaitEvent(0, eXr, 0);
    qkv_gemm<<<dim3(24, MTOT/128), 256, GEMM_SMEM>>>(bq, bk, bv);

    // flash additionally needs the packed mask (runs concurrent with qkv)
    cudaStreamWaitEvent(0, eMask, 0);
    flash_h<<<dim3(S_/64, H_, B_), 128, FLASH_SMEM>>>(Od);

    // output projection
    o_gemm<<<dim3(E_/128, MTOT/128), 256, GEMM_SMEM>>>(Od, WoT, bo, out);
}